// round 8
// baseline (speedup 1.0000x reference)
#include <cuda_runtime.h>
#include <cstdint>
#include <cstddef>

static constexpr int   B      = 8;
static constexpr int   N      = 32768;
static constexpr int   K      = 128;
static constexpr int   D      = 64;
static constexpr int   ITERS  = 10;
static constexpr float EPS    = 1e-8f;
static constexpr float LOG2E  = 1.4426950408889634f;

static constexpr int BPB   = 64;          // blocks per batch for the iteration kernel
static constexpr int NB    = B * BPB;     // 512 blocks
static constexpr int CHUNK = N / BPB;     // 512 points per block
static constexpr int TILE  = 256;         // points staged to smem per tile

static constexpr int GEMM_CH = 64;        // n-chunks per batch for node_feats GEMM -> 512 blocks
static constexpr int TN      = 32;        // points per GEMM smem tile
static constexpr int FPAD    = 4;         // s_f row padding (keeps float4 alignment)

typedef unsigned long long u64;

// ---------------- device scratch (no allocations allowed) ----------------
__device__ float g_buf[ITERS][B][K][4];   // per-iter accumulators: denom, Mx, My, Mz
__device__ float g_cinit[B][K][3];
__device__ float g_ssum[B];
__device__ float g_nfacc[B * K * D];

// ---------------- small asm helpers ----------------
__device__ __forceinline__ float ex2f(float x) {
    float r; asm("ex2.approx.ftz.f32 %0, %1;" : "=f"(r) : "f"(x)); return r;
}
__device__ __forceinline__ u64 pack2(float lo, float hi) {
    u64 r; asm("mov.b64 %0, {%1, %2};" : "=l"(r) : "f"(lo), "f"(hi)); return r;
}
__device__ __forceinline__ void unpack2(u64 v, float& lo, float& hi) {
    asm("mov.b64 {%0, %1}, %2;" : "=f"(lo), "=f"(hi) : "l"(v));
}
__device__ __forceinline__ void ffma2(u64& d, u64 a, u64 b) {
    asm("fma.rn.f32x2 %0, %1, %2, %0;" : "+l"(d) : "l"(a), "l"(b));
}
__device__ __forceinline__ u64 add2(u64 a, u64 b) {
    u64 r; asm("add.rn.f32x2 %0, %1, %2;" : "=l"(r) : "l"(a), "l"(b)); return r;
}
__device__ __forceinline__ u64 mul2(u64 a, u64 b) {
    u64 r; asm("mul.rn.f32x2 %0, %1, %2;" : "=l"(r) : "l"(a), "l"(b)); return r;
}
__device__ __forceinline__ float warp_sum(float s) {
    #pragma unroll
    for (int o = 16; o > 0; o >>= 1) s += __shfl_xor_sync(0xffffffffu, s, o);
    return s;
}

// ---------------- kernel 1: zero scratch ----------------
__global__ void k_zero() {
    int i = blockIdx.x * blockDim.x + threadIdx.x;   // launched with 65536 threads
    float* gb = &g_buf[0][0][0][0];
    if (i < ITERS * B * K * 4) gb[i] = 0.f;
    if (i < B * K * D)         g_nfacc[i] = 0.f;
}

// ---------------- kernel 2: init centers + per-batch score sums ----------------
__global__ void k_init(const float* __restrict__ xyz, const float* __restrict__ osc) {
    int b = blockIdx.x, tid = threadIdx.x;
    __shared__ float red[256];
    const float* w = osc + (size_t)b * N;
    float s = 0.f;
    for (int n = tid; n < N; n += 256) s += w[n];
    red[tid] = s;
    __syncthreads();
    for (int st = 128; st > 0; st >>= 1) {
        if (tid < st) red[tid] += red[tid + st];
        __syncthreads();
    }
    if (tid == 0) g_ssum[b] = red[0] + EPS;
    if (tid < K) {
        int n0 = tid * (N / K);
        const float* xb = xyz + (size_t)b * 3 * N;
        g_cinit[b][tid][0] = xb[n0];
        g_cinit[b][tid][1] = xb[N + n0];
        g_cinit[b][tid][2] = xb[2 * N + n0];
    }
}

// ---------------- kernel 3: one clustering iteration (launched ITERS times) ----------------
__global__ void __launch_bounds__(256)
k_iter(const float* __restrict__ xyz, const float* __restrict__ osc,
       float* __restrict__ out_gamma, int it) {
    const int b    = blockIdx.x / BPB;
    const int slot = blockIdx.x % BPB;
    const int cs   = slot * CHUNK;
    const int tid  = threadIdx.x;
    const int lane = tid & 31;
    const int wid  = tid >> 5;

    __shared__ float4 s_A[K];       // derived center constants (2*log2e*c, -log2e*|c|^2)
    __shared__ float4 s_pt[TILE];   // staged points: x0,x1,x2,w

    const float* x0p = xyz + (size_t)b * 3 * N;
    const float* x1p = x0p + N;
    const float* x2p = x0p + 2 * N;
    const float* wp  = osc + (size_t)b * N;

    // -- derive A_k from current centers --
    if (tid < K) {
        float c0, c1, c2;
        if (it == 0) {
            c0 = g_cinit[b][tid][0];
            c1 = g_cinit[b][tid][1];
            c2 = g_cinit[b][tid][2];
        } else {
            const float* pb = &g_buf[it - 1][b][tid][0];
            float inv = 1.0f / (pb[0] + EPS);
            c0 = pb[1] * inv; c1 = pb[2] * inv; c2 = pb[3] * inv;
        }
        s_A[tid] = make_float4(2.f * LOG2E * c0, 2.f * LOG2E * c1, 2.f * LOG2E * c2,
                               -LOG2E * (c0 * c0 + c1 * c1 + c2 * c2));
    }
    __syncthreads();

    // each lane owns 4 consecutive clusters; pack as f32x2 pairs (01, 23)
    const float4 A0 = s_A[lane * 4 + 0];
    const float4 A1 = s_A[lane * 4 + 1];
    const float4 A2 = s_A[lane * 4 + 2];
    const float4 A3 = s_A[lane * 4 + 3];
    const u64 Ax01 = pack2(A0.x, A1.x), Ax23 = pack2(A2.x, A3.x);
    const u64 Ay01 = pack2(A0.y, A1.y), Ay23 = pack2(A2.y, A3.y);
    const u64 Az01 = pack2(A0.z, A1.z), Az23 = pack2(A2.z, A3.z);
    const u64 Aw01 = pack2(A0.w, A1.w), Aw23 = pack2(A2.w, A3.w);

    u64 aD01 = 0, aD23 = 0, aX01 = 0, aX23 = 0;
    u64 aY01 = 0, aY23 = 0, aZ01 = 0, aZ23 = 0;

    const bool fin = (it == ITERS - 1);

    for (int tb = cs; tb < cs + CHUNK; tb += TILE) {
        int gi = tb + tid;
        float4 pd;
        pd.x = x0p[gi]; pd.y = x1p[gi]; pd.z = x2p[gi]; pd.w = wp[gi];
        __syncthreads();            // previous tile fully consumed
        s_pt[tid] = pd;
        __syncthreads();

        // 2 points per loop step -> two independent MUFU/shuffle chains in flight
        #pragma unroll 2
        for (int j = 0; j < TILE / 16; ++j) {
            #pragma unroll
            for (int h = 0; h < 2; ++h) {
                const int p = wid + j * 16 + h * 8;
                const float4 P = s_pt[p];
                float q = P.x * P.x;
                q = fmaf(P.y, P.y, q);
                q = fmaf(P.z, P.z, q);
                q = -LOG2E * q;

                const u64 qq  = pack2(q, q);
                const u64 Pxx = pack2(P.x, P.x);
                const u64 Pyy = pack2(P.y, P.y);
                const u64 Pzz = pack2(P.z, P.z);

                u64 t01 = add2(Aw01, qq);
                ffma2(t01, Ax01, Pxx); ffma2(t01, Ay01, Pyy); ffma2(t01, Az01, Pzz);
                u64 t23 = add2(Aw23, qq);
                ffma2(t23, Ax23, Pxx); ffma2(t23, Ay23, Pyy); ffma2(t23, Az23, Pzz);

                float t0, t1, t2, t3;
                unpack2(t01, t0, t1); unpack2(t23, t2, t3);
                const float e0 = ex2f(t0), e1 = ex2f(t1), e2 = ex2f(t2), e3 = ex2f(t3);

                float s = (e0 + e1) + (e2 + e3);
                s = warp_sum(s);
                const float u = __fdividef(P.w, s);

                const u64 uu  = pack2(u, u);
                const u64 g01 = mul2(pack2(e0, e1), uu);
                const u64 g23 = mul2(pack2(e2, e3), uu);

                aD01 = add2(aD01, g01);      aD23 = add2(aD23, g23);
                ffma2(aX01, g01, Pxx);       ffma2(aX23, g23, Pxx);
                ffma2(aY01, g01, Pyy);       ffma2(aY23, g23, Pyy);
                ffma2(aZ01, g01, Pzz);       ffma2(aZ23, g23, Pzz);

                if (fin) {
                    float g0, g1, g2, g3;
                    unpack2(g01, g0, g1); unpack2(g23, g2, g3);
                    *(float4*)&out_gamma[((size_t)(b * N + tb + p)) * K + lane * 4]
                        = make_float4(g0, g1, g2, g3);
                }
            }
        }
    }

    // -- flush register accumulators to global --
    float d0, d1, d2, d3, x0, x1, x2, x3, y0, y1, y2, y3, z0, z1, z2, z3;
    unpack2(aD01, d0, d1); unpack2(aD23, d2, d3);
    unpack2(aX01, x0, x1); unpack2(aX23, x2, x3);
    unpack2(aY01, y0, y1); unpack2(aY23, y2, y3);
    unpack2(aZ01, z0, z1); unpack2(aZ23, z2, z3);
    float* pb = &g_buf[it][b][lane * 4][0];
    atomicAdd(pb + 0,  d0); atomicAdd(pb + 1,  x0); atomicAdd(pb + 2,  y0); atomicAdd(pb + 3,  z0);
    atomicAdd(pb + 4,  d1); atomicAdd(pb + 5,  x1); atomicAdd(pb + 6,  y1); atomicAdd(pb + 7,  z1);
    atomicAdd(pb + 8,  d2); atomicAdd(pb + 9,  x2); atomicAdd(pb + 10, y2); atomicAdd(pb + 11, z2);
    atomicAdd(pb + 12, d3); atomicAdd(pb + 13, x3); atomicAdd(pb + 14, y3); atomicAdd(pb + 15, z3);
}

// ---------------- kernel 4: finalize pi / node_xyz ----------------
__global__ void k_fin(float* __restrict__ out_pi, float* __restrict__ out_nxyz) {
    int b = blockIdx.x, k = threadIdx.x;   // <<<B, K>>>
    const float* pb = &g_buf[ITERS - 1][b][k][0];
    float raw = pb[0];
    float inv = 1.0f / (raw + EPS);
    out_pi[b * K + k] = raw / g_ssum[b];
    out_nxyz[(b * K + k) * 3 + 0] = pb[1] * inv;
    out_nxyz[(b * K + k) * 3 + 1] = pb[2] * inv;
    out_nxyz[(b * K + k) * 3 + 2] = pb[3] * inv;
}

// ---------------- kernel 5: node_feats = gamma^T @ feats (split-N, f32x2 FMA) ----------------
__global__ void __launch_bounds__(128)
k_nf(const float* __restrict__ feats, const float* __restrict__ gamma) {
    const int b  = blockIdx.y;
    const int n0 = blockIdx.x * (N / GEMM_CH);
    const int tid = threadIdx.x;
    const int k0 = (tid >> 3) * 8;   // 16 k-groups of 8
    const int d0 = (tid & 7) * 8;    // 8 d-groups of 8

    __shared__ float s_g[TN][K];          // 16 KB
    __shared__ float s_f[TN][D + FPAD];   // padded by 4 -> float4-aligned rows

    u64 acc[8][4];
    #pragma unroll
    for (int i = 0; i < 8; i++)
        #pragma unroll
        for (int c = 0; c < 4; c++) acc[i][c] = pack2(0.f, 0.f);

    const float* gbase = gamma + (size_t)b * N * K;
    const float* fbase = feats + (size_t)b * D * N;

    for (int t0 = n0; t0 < n0 + N / GEMM_CH; t0 += TN) {
        __syncthreads();
        {   // gamma tile: TN*K floats = 1024 float4, 8 per thread, coalesced
            const float4* src = (const float4*)(gbase + (size_t)t0 * K);
            float4* dst = (float4*)&s_g[0][0];
            #pragma unroll
            for (int j = 0; j < 8; j++) dst[tid + j * 128] = src[tid + j * 128];
        }
        {   // feats tile: D rows of TN consecutive n, transposed into s_f[n][d]
            #pragma unroll
            for (int j = 0; j < 16; j++) {
                int li = tid + j * 128;          // 0..2047
                int d = li >> 5, i = li & 31;
                s_f[i][d] = fbase[(size_t)d * N + t0 + i];
            }
        }
        __syncthreads();

        for (int i = 0; i < TN; i++) {
            float4 ga  = *(const float4*)&s_g[i][k0];
            float4 gb2 = *(const float4*)&s_g[i][k0 + 4];
            float4 fa  = *(const float4*)&s_f[i][d0];
            float4 fb  = *(const float4*)&s_f[i][d0 + 4];
            u64 f01 = pack2(fa.x, fa.y), f23 = pack2(fa.z, fa.w);
            u64 f45 = pack2(fb.x, fb.y), f67 = pack2(fb.z, fb.w);
            float gk[8] = {ga.x, ga.y, ga.z, ga.w, gb2.x, gb2.y, gb2.z, gb2.w};
            #pragma unroll
            for (int kk = 0; kk < 8; kk++) {
                u64 gg = pack2(gk[kk], gk[kk]);
                ffma2(acc[kk][0], gg, f01);
                ffma2(acc[kk][1], gg, f23);
                ffma2(acc[kk][2], gg, f45);
                ffma2(acc[kk][3], gg, f67);
            }
        }
    }

    #pragma unroll
    for (int kk = 0; kk < 8; kk++)
        #pragma unroll
        for (int c = 0; c < 4; c++) {
            float lo, hi; unpack2(acc[kk][c], lo, hi);
            float* dst = &g_nfacc[((size_t)b * K + (k0 + kk)) * D + d0 + c * 2];
            atomicAdd(dst, lo);
            atomicAdd(dst + 1, hi);
        }
}

// ---------------- kernel 6: divide node_feats by denom ----------------
__global__ void k_nf_fin(float* __restrict__ out_nf) {
    int i = blockIdx.x * blockDim.x + threadIdx.x;   // 65536 threads
    if (i < B * K * D) {
        int b = i / (K * D);
        int k = (i % (K * D)) / D;
        float dn = g_buf[ITERS - 1][b][k][0] + EPS;
        out_nf[i] = g_nfacc[i] / dn;
    }
}

// ---------------- launch ----------------
extern "C" void kernel_launch(void* const* d_in, const int* in_sizes, int n_in,
                              void* d_out, int out_size) {
    const float* xyz   = (const float*)d_in[0];
    const float* feats = (const float*)d_in[1];
    const float* osc   = (const float*)d_in[2];

    float* out   = (float*)d_out;
    float* ogam  = out;
    float* opi   = ogam + (size_t)B * N * K;
    float* oxyz  = opi + B * K;
    float* onf   = oxyz + B * K * 3;

    k_zero<<<256, 256>>>();
    k_init<<<B, 256>>>(xyz, osc);
    for (int it = 0; it < ITERS; ++it)
        k_iter<<<NB, 256>>>(xyz, osc, ogam, it);
    k_fin<<<B, K>>>(opi, oxyz);
    dim3 gg(GEMM_CH, B);
    k_nf<<<gg, 128>>>(feats, ogam);
    k_nf_fin<<<256, 256>>>(onf);
}

// round 9
// speedup vs baseline: 1.0318x; 1.0318x over previous
#include <cuda_runtime.h>
#include <cstdint>
#include <cstddef>

static constexpr int   B      = 8;
static constexpr int   N      = 32768;
static constexpr int   K      = 128;
static constexpr int   D      = 64;
static constexpr int   ITERS  = 10;
static constexpr float EPS    = 1e-8f;
static constexpr float LOG2E  = 1.4426950408889634f;

static constexpr int BPB   = 64;          // blocks per batch for the iteration kernel
static constexpr int NB    = B * BPB;     // 512 blocks
static constexpr int CHUNK = N / BPB;     // 512 points per block
static constexpr int TILE  = 256;         // points staged to smem per tile

static constexpr int GEMM_CH = 64;        // n-chunks per batch for node_feats GEMM -> 512 blocks
static constexpr int TN      = 32;        // points per GEMM smem tile
static constexpr int FPAD    = 4;         // s_f row padding (keeps float4 alignment)

typedef unsigned long long u64;

// ---------------- device scratch (no allocations allowed) ----------------
__device__ float g_buf[ITERS][B][K][4];   // per-iter accumulators: denom, Mx, My, Mz
__device__ float g_cinit[B][K][3];
__device__ float g_ssum[B];
__device__ float g_nfacc[B * K * D];

// ---------------- small asm helpers ----------------
__device__ __forceinline__ float ex2f(float x) {
    float r; asm("ex2.approx.ftz.f32 %0, %1;" : "=f"(r) : "f"(x)); return r;
}
__device__ __forceinline__ u64 pack2(float lo, float hi) {
    u64 r; asm("mov.b64 %0, {%1, %2};" : "=l"(r) : "f"(lo), "f"(hi)); return r;
}
__device__ __forceinline__ void unpack2(u64 v, float& lo, float& hi) {
    asm("mov.b64 {%0, %1}, %2;" : "=f"(lo), "=f"(hi) : "l"(v));
}
__device__ __forceinline__ void ffma2(u64& d, u64 a, u64 b) {
    asm("fma.rn.f32x2 %0, %1, %2, %0;" : "+l"(d) : "l"(a), "l"(b));
}

// ---------------- kernel 1: zero scratch ----------------
__global__ void k_zero() {
    int i = blockIdx.x * blockDim.x + threadIdx.x;   // launched with 65536 threads
    float* gb = &g_buf[0][0][0][0];
    if (i < ITERS * B * K * 4) gb[i] = 0.f;
    if (i < B * K * D)         g_nfacc[i] = 0.f;
}

// ---------------- kernel 2: init centers + per-batch score sums ----------------
__global__ void k_init(const float* __restrict__ xyz, const float* __restrict__ osc) {
    int b = blockIdx.x, tid = threadIdx.x;
    __shared__ float red[256];
    const float* w = osc + (size_t)b * N;
    float s = 0.f;
    for (int n = tid; n < N; n += 256) s += w[n];
    red[tid] = s;
    __syncthreads();
    for (int st = 128; st > 0; st >>= 1) {
        if (tid < st) red[tid] += red[tid + st];
        __syncthreads();
    }
    if (tid == 0) g_ssum[b] = red[0] + EPS;
    if (tid < K) {
        int n0 = tid * (N / K);
        const float* xb = xyz + (size_t)b * 3 * N;
        g_cinit[b][tid][0] = xb[n0];
        g_cinit[b][tid][1] = xb[N + n0];
        g_cinit[b][tid][2] = xb[2 * N + n0];
    }
}

// ---------------- kernel 3: one clustering iteration (launched ITERS times) ----------------
// scalar math, 4 independent point-chains in flight per warp
__global__ void __launch_bounds__(256, 2)
k_iter(const float* __restrict__ xyz, const float* __restrict__ osc,
       float* __restrict__ out_gamma, int it) {
    const int b    = blockIdx.x / BPB;
    const int slot = blockIdx.x % BPB;
    const int cs   = slot * CHUNK;
    const int tid  = threadIdx.x;
    const int lane = tid & 31;
    const int wid  = tid >> 5;

    __shared__ float4 s_A[K];       // derived center constants (2*log2e*c, -log2e*|c|^2)
    __shared__ float4 s_pt[TILE];   // staged points: x0,x1,x2,w

    const float* x0p = xyz + (size_t)b * 3 * N;
    const float* x1p = x0p + N;
    const float* x2p = x0p + 2 * N;
    const float* wp  = osc + (size_t)b * N;

    // -- derive A_k from current centers --
    if (tid < K) {
        float c0, c1, c2;
        if (it == 0) {
            c0 = g_cinit[b][tid][0];
            c1 = g_cinit[b][tid][1];
            c2 = g_cinit[b][tid][2];
        } else {
            const float* pb = &g_buf[it - 1][b][tid][0];
            float inv = 1.0f / (pb[0] + EPS);
            c0 = pb[1] * inv; c1 = pb[2] * inv; c2 = pb[3] * inv;
        }
        s_A[tid] = make_float4(2.f * LOG2E * c0, 2.f * LOG2E * c1, 2.f * LOG2E * c2,
                               -LOG2E * (c0 * c0 + c1 * c1 + c2 * c2));
    }
    __syncthreads();

    // each lane owns 4 consecutive clusters
    const float4 A0 = s_A[lane * 4 + 0];
    const float4 A1 = s_A[lane * 4 + 1];
    const float4 A2 = s_A[lane * 4 + 2];
    const float4 A3 = s_A[lane * 4 + 3];

    float aD0 = 0.f, aD1 = 0.f, aD2 = 0.f, aD3 = 0.f;
    float aX0 = 0.f, aX1 = 0.f, aX2 = 0.f, aX3 = 0.f;
    float aY0 = 0.f, aY1 = 0.f, aY2 = 0.f, aY3 = 0.f;
    float aZ0 = 0.f, aZ1 = 0.f, aZ2 = 0.f, aZ3 = 0.f;

    const bool fin = (it == ITERS - 1);

    for (int tb = cs; tb < cs + CHUNK; tb += TILE) {
        int gi = tb + tid;
        float4 pd;
        pd.x = x0p[gi]; pd.y = x1p[gi]; pd.z = x2p[gi]; pd.w = wp[gi];
        __syncthreads();            // previous tile fully consumed
        s_pt[tid] = pd;
        __syncthreads();

        // each warp: 32 points, processed 4 at a time (4 independent chains)
        for (int m = 0; m < 32; m += 4) {
            float4 P[4];
            float  e0[4], e1[4], e2[4], e3[4], s[4], u[4];

            #pragma unroll
            for (int i = 0; i < 4; ++i)
                P[i] = s_pt[wid + (m + i) * 8];

            #pragma unroll
            for (int i = 0; i < 4; ++i) {
                float q = P[i].x * P[i].x;
                q = fmaf(P[i].y, P[i].y, q);
                q = fmaf(P[i].z, P[i].z, q);
                q = -LOG2E * q;

                float t0 = A0.w + q; t0 = fmaf(A0.x, P[i].x, t0); t0 = fmaf(A0.y, P[i].y, t0); t0 = fmaf(A0.z, P[i].z, t0);
                float t1 = A1.w + q; t1 = fmaf(A1.x, P[i].x, t1); t1 = fmaf(A1.y, P[i].y, t1); t1 = fmaf(A1.z, P[i].z, t1);
                float t2 = A2.w + q; t2 = fmaf(A2.x, P[i].x, t2); t2 = fmaf(A2.y, P[i].y, t2); t2 = fmaf(A2.z, P[i].z, t2);
                float t3 = A3.w + q; t3 = fmaf(A3.x, P[i].x, t3); t3 = fmaf(A3.y, P[i].y, t3); t3 = fmaf(A3.z, P[i].z, t3);

                e0[i] = ex2f(t0); e1[i] = ex2f(t1); e2[i] = ex2f(t2); e3[i] = ex2f(t3);
                s[i] = (e0[i] + e1[i]) + (e2[i] + e3[i]);
            }

            // 4 interleaved butterfly reductions (chains pipeline through SHFL unit)
            #pragma unroll
            for (int o = 16; o > 0; o >>= 1) {
                #pragma unroll
                for (int i = 0; i < 4; ++i)
                    s[i] += __shfl_xor_sync(0xffffffffu, s[i], o);
            }

            #pragma unroll
            for (int i = 0; i < 4; ++i)
                u[i] = __fdividef(P[i].w, s[i]);

            #pragma unroll
            for (int i = 0; i < 4; ++i) {
                float g0 = e0[i] * u[i], g1 = e1[i] * u[i];
                float g2 = e2[i] * u[i], g3 = e3[i] * u[i];

                aD0 += g0; aX0 = fmaf(g0, P[i].x, aX0); aY0 = fmaf(g0, P[i].y, aY0); aZ0 = fmaf(g0, P[i].z, aZ0);
                aD1 += g1; aX1 = fmaf(g1, P[i].x, aX1); aY1 = fmaf(g1, P[i].y, aY1); aZ1 = fmaf(g1, P[i].z, aZ1);
                aD2 += g2; aX2 = fmaf(g2, P[i].x, aX2); aY2 = fmaf(g2, P[i].y, aY2); aZ2 = fmaf(g2, P[i].z, aZ2);
                aD3 += g3; aX3 = fmaf(g3, P[i].x, aX3); aY3 = fmaf(g3, P[i].y, aY3); aZ3 = fmaf(g3, P[i].z, aZ3);

                if (fin) {
                    *(float4*)&out_gamma[((size_t)(b * N + tb + wid + (m + i) * 8)) * K + lane * 4]
                        = make_float4(g0, g1, g2, g3);
                }
            }
        }
    }

    // -- flush register accumulators to global --
    float* pb = &g_buf[it][b][lane * 4][0];
    atomicAdd(pb + 0,  aD0); atomicAdd(pb + 1,  aX0); atomicAdd(pb + 2,  aY0); atomicAdd(pb + 3,  aZ0);
    atomicAdd(pb + 4,  aD1); atomicAdd(pb + 5,  aX1); atomicAdd(pb + 6,  aY1); atomicAdd(pb + 7,  aZ1);
    atomicAdd(pb + 8,  aD2); atomicAdd(pb + 9,  aX2); atomicAdd(pb + 10, aY2); atomicAdd(pb + 11, aZ2);
    atomicAdd(pb + 12, aD3); atomicAdd(pb + 13, aX3); atomicAdd(pb + 14, aY3); atomicAdd(pb + 15, aZ3);
}

// ---------------- kernel 4: finalize pi / node_xyz ----------------
__global__ void k_fin(float* __restrict__ out_pi, float* __restrict__ out_nxyz) {
    int b = blockIdx.x, k = threadIdx.x;   // <<<B, K>>>
    const float* pb = &g_buf[ITERS - 1][b][k][0];
    float raw = pb[0];
    float inv = 1.0f / (raw + EPS);
    out_pi[b * K + k] = raw / g_ssum[b];
    out_nxyz[(b * K + k) * 3 + 0] = pb[1] * inv;
    out_nxyz[(b * K + k) * 3 + 1] = pb[2] * inv;
    out_nxyz[(b * K + k) * 3 + 2] = pb[3] * inv;
}

// ---------------- kernel 5: node_feats = gamma^T @ feats (split-N, f32x2 FMA) ----------------
__global__ void __launch_bounds__(128)
k_nf(const float* __restrict__ feats, const float* __restrict__ gamma) {
    const int b  = blockIdx.y;
    const int n0 = blockIdx.x * (N / GEMM_CH);
    const int tid = threadIdx.x;
    const int k0 = (tid >> 3) * 8;   // 16 k-groups of 8
    const int d0 = (tid & 7) * 8;    // 8 d-groups of 8

    __shared__ float s_g[TN][K];          // 16 KB
    __shared__ float s_f[TN][D + FPAD];   // padded by 4 -> float4-aligned rows

    u64 acc[8][4];
    #pragma unroll
    for (int i = 0; i < 8; i++)
        #pragma unroll
        for (int c = 0; c < 4; c++) acc[i][c] = pack2(0.f, 0.f);

    const float* gbase = gamma + (size_t)b * N * K;
    const float* fbase = feats + (size_t)b * D * N;

    for (int t0 = n0; t0 < n0 + N / GEMM_CH; t0 += TN) {
        __syncthreads();
        {   // gamma tile: TN*K floats = 1024 float4, 8 per thread, coalesced
            const float4* src = (const float4*)(gbase + (size_t)t0 * K);
            float4* dst = (float4*)&s_g[0][0];
            #pragma unroll
            for (int j = 0; j < 8; j++) dst[tid + j * 128] = src[tid + j * 128];
        }
        {   // feats tile: D rows of TN consecutive n, transposed into s_f[n][d]
            #pragma unroll
            for (int j = 0; j < 16; j++) {
                int li = tid + j * 128;          // 0..2047
                int d = li >> 5, i = li & 31;
                s_f[i][d] = fbase[(size_t)d * N + t0 + i];
            }
        }
        __syncthreads();

        for (int i = 0; i < TN; i++) {
            float4 ga  = *(const float4*)&s_g[i][k0];
            float4 gb2 = *(const float4*)&s_g[i][k0 + 4];
            float4 fa  = *(const float4*)&s_f[i][d0];
            float4 fb  = *(const float4*)&s_f[i][d0 + 4];
            u64 f01 = pack2(fa.x, fa.y), f23 = pack2(fa.z, fa.w);
            u64 f45 = pack2(fb.x, fb.y), f67 = pack2(fb.z, fb.w);
            float gk[8] = {ga.x, ga.y, ga.z, ga.w, gb2.x, gb2.y, gb2.z, gb2.w};
            #pragma unroll
            for (int kk = 0; kk < 8; kk++) {
                u64 gg = pack2(gk[kk], gk[kk]);
                ffma2(acc[kk][0], gg, f01);
                ffma2(acc[kk][1], gg, f23);
                ffma2(acc[kk][2], gg, f45);
                ffma2(acc[kk][3], gg, f67);
            }
        }
    }

    #pragma unroll
    for (int kk = 0; kk < 8; kk++)
        #pragma unroll
        for (int c = 0; c < 4; c++) {
            float lo, hi; unpack2(acc[kk][c], lo, hi);
            float* dst = &g_nfacc[((size_t)b * K + (k0 + kk)) * D + d0 + c * 2];
            atomicAdd(dst, lo);
            atomicAdd(dst + 1, hi);
        }
}

// ---------------- kernel 6: divide node_feats by denom ----------------
__global__ void k_nf_fin(float* __restrict__ out_nf) {
    int i = blockIdx.x * blockDim.x + threadIdx.x;   // 65536 threads
    if (i < B * K * D) {
        int b = i / (K * D);
        int k = (i % (K * D)) / D;
        float dn = g_buf[ITERS - 1][b][k][0] + EPS;
        out_nf[i] = g_nfacc[i] / dn;
    }
}

// ---------------- launch ----------------
extern "C" void kernel_launch(void* const* d_in, const int* in_sizes, int n_in,
                              void* d_out, int out_size) {
    const float* xyz   = (const float*)d_in[0];
    const float* feats = (const float*)d_in[1];
    const float* osc   = (const float*)d_in[2];

    float* out   = (float*)d_out;
    float* ogam  = out;
    float* opi   = ogam + (size_t)B * N * K;
    float* oxyz  = opi + B * K;
    float* onf   = oxyz + B * K * 3;

    k_zero<<<256, 256>>>();
    k_init<<<B, 256>>>(xyz, osc);
    for (int it = 0; it < ITERS; ++it)
        k_iter<<<NB, 256>>>(xyz, osc, ogam, it);
    k_fin<<<B, K>>>(opi, oxyz);
    dim3 gg(GEMM_CH, B);
    k_nf<<<gg, 128>>>(feats, ogam);
    k_nf_fin<<<256, 256>>>(onf);
}

// round 10
// speedup vs baseline: 1.1172x; 1.0828x over previous
#include <cuda_runtime.h>
#include <cstdint>
#include <cstddef>

static constexpr int   B      = 8;
static constexpr int   N      = 32768;
static constexpr int   K      = 128;
static constexpr int   D      = 64;
static constexpr int   ITERS  = 10;
static constexpr float EPS    = 1e-8f;
static constexpr float LOG2E  = 1.4426950408889634f;

static constexpr int BPB   = 56;          // blocks per batch -> 448 blocks ~= 3/SM, one wave
static constexpr int NB    = B * BPB;     // 448 blocks
static constexpr int TILE  = 256;         // points staged to smem per tile

static constexpr int GEMM_CH = 64;        // n-chunks per batch for node_feats GEMM -> 512 blocks
static constexpr int TN      = 32;        // points per GEMM smem tile
static constexpr int FPAD    = 4;         // s_f row padding (keeps float4 alignment)

typedef unsigned long long u64;

// ---------------- device scratch (no allocations allowed) ----------------
__device__ float g_buf[ITERS][B][K][4];   // per-iter accumulators: denom, Mx, My, Mz
__device__ float g_cinit[B][K][3];
__device__ float g_ssum[B];
__device__ float g_nfacc[B * K * D];

// ---------------- small asm helpers ----------------
__device__ __forceinline__ float ex2f(float x) {
    float r; asm("ex2.approx.ftz.f32 %0, %1;" : "=f"(r) : "f"(x)); return r;
}
__device__ __forceinline__ u64 pack2(float lo, float hi) {
    u64 r; asm("mov.b64 %0, {%1, %2};" : "=l"(r) : "f"(lo), "f"(hi)); return r;
}
__device__ __forceinline__ void unpack2(u64 v, float& lo, float& hi) {
    asm("mov.b64 {%0, %1}, %2;" : "=f"(lo), "=f"(hi) : "l"(v));
}
__device__ __forceinline__ void ffma2(u64& d, u64 a, u64 b) {
    asm("fma.rn.f32x2 %0, %1, %2, %0;" : "+l"(d) : "l"(a), "l"(b));
}

// ---------------- kernel 1: zero scratch ----------------
__global__ void k_zero() {
    int i = blockIdx.x * blockDim.x + threadIdx.x;   // launched with 65536 threads
    float* gb = &g_buf[0][0][0][0];
    if (i < ITERS * B * K * 4) gb[i] = 0.f;
    if (i < B * K * D)         g_nfacc[i] = 0.f;
}

// ---------------- kernel 2: init centers + per-batch score sums ----------------
__global__ void k_init(const float* __restrict__ xyz, const float* __restrict__ osc) {
    int b = blockIdx.x, tid = threadIdx.x;
    __shared__ float red[256];
    const float* w = osc + (size_t)b * N;
    float s = 0.f;
    for (int n = tid; n < N; n += 256) s += w[n];
    red[tid] = s;
    __syncthreads();
    for (int st = 128; st > 0; st >>= 1) {
        if (tid < st) red[tid] += red[tid + st];
        __syncthreads();
    }
    if (tid == 0) g_ssum[b] = red[0] + EPS;
    if (tid < K) {
        int n0 = tid * (N / K);
        const float* xb = xyz + (size_t)b * 3 * N;
        g_cinit[b][tid][0] = xb[n0];
        g_cinit[b][tid][1] = xb[N + n0];
        g_cinit[b][tid][2] = xb[2 * N + n0];
    }
}

// ---------------- kernel 3: one clustering iteration (launched ITERS times) ----------------
// R5's lean scalar body; q-term dropped (softmax shift invariance); wave-balanced grid.
__global__ void __launch_bounds__(256, 3)
k_iter(const float* __restrict__ xyz, const float* __restrict__ osc,
       float* __restrict__ out_gamma, int it) {
    const int b    = blockIdx.x / BPB;
    const int slot = blockIdx.x % BPB;
    const int cs   = (int)(((long long)slot * N) / BPB);
    const int ce   = (int)(((long long)(slot + 1) * N) / BPB);
    const int tid  = threadIdx.x;
    const int lane = tid & 31;
    const int wid  = tid >> 5;

    __shared__ float4 s_A[K];       // derived center constants (2*log2e*c, -log2e*|c|^2)
    __shared__ float4 s_pt[TILE];   // staged points: x0,x1,x2,w

    const float* x0p = xyz + (size_t)b * 3 * N;
    const float* x1p = x0p + N;
    const float* x2p = x0p + 2 * N;
    const float* wp  = osc + (size_t)b * N;

    // -- derive A_k from current centers --
    if (tid < K) {
        float c0, c1, c2;
        if (it == 0) {
            c0 = g_cinit[b][tid][0];
            c1 = g_cinit[b][tid][1];
            c2 = g_cinit[b][tid][2];
        } else {
            const float* pb = &g_buf[it - 1][b][tid][0];
            float inv = 1.0f / (pb[0] + EPS);
            c0 = pb[1] * inv; c1 = pb[2] * inv; c2 = pb[3] * inv;
        }
        s_A[tid] = make_float4(2.f * LOG2E * c0, 2.f * LOG2E * c1, 2.f * LOG2E * c2,
                               -LOG2E * (c0 * c0 + c1 * c1 + c2 * c2));
    }
    __syncthreads();

    // each lane owns 4 consecutive clusters
    const float4 A0 = s_A[lane * 4 + 0];
    const float4 A1 = s_A[lane * 4 + 1];
    const float4 A2 = s_A[lane * 4 + 2];
    const float4 A3 = s_A[lane * 4 + 3];

    float aD0 = 0.f, aD1 = 0.f, aD2 = 0.f, aD3 = 0.f;
    float aX0 = 0.f, aX1 = 0.f, aX2 = 0.f, aX3 = 0.f;
    float aY0 = 0.f, aY1 = 0.f, aY2 = 0.f, aY3 = 0.f;
    float aZ0 = 0.f, aZ1 = 0.f, aZ2 = 0.f, aZ3 = 0.f;

    const bool fin = (it == ITERS - 1);

    for (int tb = cs; tb < ce; tb += TILE) {
        int gi = tb + tid;
        float4 pd = make_float4(0.f, 0.f, 0.f, 0.f);
        if (gi < ce) { pd.x = x0p[gi]; pd.y = x1p[gi]; pd.z = x2p[gi]; pd.w = wp[gi]; }
        __syncthreads();            // previous tile fully consumed
        s_pt[tid] = pd;
        __syncthreads();

        int tn = ce - tb; if (tn > TILE) tn = TILE;

        for (int p = wid; p < tn; p += 8) {
            float4 P = s_pt[p];

            // q (point-norm term) dropped: constant across k, cancels in softmax
            float t0 = fmaf(A0.x, P.x, A0.w); t0 = fmaf(A0.y, P.y, t0); t0 = fmaf(A0.z, P.z, t0);
            float t1 = fmaf(A1.x, P.x, A1.w); t1 = fmaf(A1.y, P.y, t1); t1 = fmaf(A1.z, P.z, t1);
            float t2 = fmaf(A2.x, P.x, A2.w); t2 = fmaf(A2.y, P.y, t2); t2 = fmaf(A2.z, P.z, t2);
            float t3 = fmaf(A3.x, P.x, A3.w); t3 = fmaf(A3.y, P.y, t3); t3 = fmaf(A3.z, P.z, t3);

            float e0 = ex2f(t0), e1 = ex2f(t1), e2 = ex2f(t2), e3 = ex2f(t3);
            float s = (e0 + e1) + (e2 + e3);
            #pragma unroll
            for (int o = 16; o > 0; o >>= 1) s += __shfl_xor_sync(0xffffffffu, s, o);

            float u = __fdividef(P.w, s);
            float g0 = e0 * u, g1 = e1 * u, g2 = e2 * u, g3 = e3 * u;

            aD0 += g0; aX0 = fmaf(g0, P.x, aX0); aY0 = fmaf(g0, P.y, aY0); aZ0 = fmaf(g0, P.z, aZ0);
            aD1 += g1; aX1 = fmaf(g1, P.x, aX1); aY1 = fmaf(g1, P.y, aY1); aZ1 = fmaf(g1, P.z, aZ1);
            aD2 += g2; aX2 = fmaf(g2, P.x, aX2); aY2 = fmaf(g2, P.y, aY2); aZ2 = fmaf(g2, P.z, aZ2);
            aD3 += g3; aX3 = fmaf(g3, P.x, aX3); aY3 = fmaf(g3, P.y, aY3); aZ3 = fmaf(g3, P.z, aZ3);

            if (fin) {
                float4 gv = make_float4(g0, g1, g2, g3);
                *(float4*)&out_gamma[((size_t)(b * N + tb + p)) * K + lane * 4] = gv;
            }
        }
    }

    // -- flush register accumulators to global --
    float* pb = &g_buf[it][b][lane * 4][0];
    atomicAdd(pb + 0,  aD0); atomicAdd(pb + 1,  aX0); atomicAdd(pb + 2,  aY0); atomicAdd(pb + 3,  aZ0);
    atomicAdd(pb + 4,  aD1); atomicAdd(pb + 5,  aX1); atomicAdd(pb + 6,  aY1); atomicAdd(pb + 7,  aZ1);
    atomicAdd(pb + 8,  aD2); atomicAdd(pb + 9,  aX2); atomicAdd(pb + 10, aY2); atomicAdd(pb + 11, aZ2);
    atomicAdd(pb + 12, aD3); atomicAdd(pb + 13, aX3); atomicAdd(pb + 14, aY3); atomicAdd(pb + 15, aZ3);
}

// ---------------- kernel 4: finalize pi / node_xyz ----------------
__global__ void k_fin(float* __restrict__ out_pi, float* __restrict__ out_nxyz) {
    int b = blockIdx.x, k = threadIdx.x;   // <<<B, K>>>
    const float* pb = &g_buf[ITERS - 1][b][k][0];
    float raw = pb[0];
    float inv = 1.0f / (raw + EPS);
    out_pi[b * K + k] = raw / g_ssum[b];
    out_nxyz[(b * K + k) * 3 + 0] = pb[1] * inv;
    out_nxyz[(b * K + k) * 3 + 1] = pb[2] * inv;
    out_nxyz[(b * K + k) * 3 + 2] = pb[3] * inv;
}

// ---------------- kernel 5: node_feats = gamma^T @ feats (split-N, f32x2 FMA) ----------------
__global__ void __launch_bounds__(128)
k_nf(const float* __restrict__ feats, const float* __restrict__ gamma) {
    const int b  = blockIdx.y;
    const int n0 = blockIdx.x * (N / GEMM_CH);
    const int tid = threadIdx.x;
    const int k0 = (tid >> 3) * 8;   // 16 k-groups of 8
    const int d0 = (tid & 7) * 8;    // 8 d-groups of 8

    __shared__ float s_g[TN][K];          // 16 KB
    __shared__ float s_f[TN][D + FPAD];   // padded by 4 -> float4-aligned rows

    u64 acc[8][4];
    #pragma unroll
    for (int i = 0; i < 8; i++)
        #pragma unroll
        for (int c = 0; c < 4; c++) acc[i][c] = pack2(0.f, 0.f);

    const float* gbase = gamma + (size_t)b * N * K;
    const float* fbase = feats + (size_t)b * D * N;

    for (int t0 = n0; t0 < n0 + N / GEMM_CH; t0 += TN) {
        __syncthreads();
        {   // gamma tile: TN*K floats = 1024 float4, 8 per thread, coalesced
            const float4* src = (const float4*)(gbase + (size_t)t0 * K);
            float4* dst = (float4*)&s_g[0][0];
            #pragma unroll
            for (int j = 0; j < 8; j++) dst[tid + j * 128] = src[tid + j * 128];
        }
        {   // feats tile: D rows of TN consecutive n, transposed into s_f[n][d]
            #pragma unroll
            for (int j = 0; j < 16; j++) {
                int li = tid + j * 128;          // 0..2047
                int d = li >> 5, i = li & 31;
                s_f[i][d] = fbase[(size_t)d * N + t0 + i];
            }
        }
        __syncthreads();

        for (int i = 0; i < TN; i++) {
            float4 ga  = *(const float4*)&s_g[i][k0];
            float4 gb2 = *(const float4*)&s_g[i][k0 + 4];
            float4 fa  = *(const float4*)&s_f[i][d0];
            float4 fb  = *(const float4*)&s_f[i][d0 + 4];
            u64 f01 = pack2(fa.x, fa.y), f23 = pack2(fa.z, fa.w);
            u64 f45 = pack2(fb.x, fb.y), f67 = pack2(fb.z, fb.w);
            float gk[8] = {ga.x, ga.y, ga.z, ga.w, gb2.x, gb2.y, gb2.z, gb2.w};
            #pragma unroll
            for (int kk = 0; kk < 8; kk++) {
                u64 gg = pack2(gk[kk], gk[kk]);
                ffma2(acc[kk][0], gg, f01);
                ffma2(acc[kk][1], gg, f23);
                ffma2(acc[kk][2], gg, f45);
                ffma2(acc[kk][3], gg, f67);
            }
        }
    }

    #pragma unroll
    for (int kk = 0; kk < 8; kk++)
        #pragma unroll
        for (int c = 0; c < 4; c++) {
            float lo, hi; unpack2(acc[kk][c], lo, hi);
            float* dst = &g_nfacc[((size_t)b * K + (k0 + kk)) * D + d0 + c * 2];
            atomicAdd(dst, lo);
            atomicAdd(dst + 1, hi);
        }
}

// ---------------- kernel 6: divide node_feats by denom ----------------
__global__ void k_nf_fin(float* __restrict__ out_nf) {
    int i = blockIdx.x * blockDim.x + threadIdx.x;   // 65536 threads
    if (i < B * K * D) {
        int b = i / (K * D);
        int k = (i % (K * D)) / D;
        float dn = g_buf[ITERS - 1][b][k][0] + EPS;
        out_nf[i] = g_nfacc[i] / dn;
    }
}

// ---------------- launch ----------------
extern "C" void kernel_launch(void* const* d_in, const int* in_sizes, int n_in,
                              void* d_out, int out_size) {
    const float* xyz   = (const float*)d_in[0];
    const float* feats = (const float*)d_in[1];
    const float* osc   = (const float*)d_in[2];

    float* out   = (float*)d_out;
    float* ogam  = out;
    float* opi   = ogam + (size_t)B * N * K;
    float* oxyz  = opi + B * K;
    float* onf   = oxyz + B * K * 3;

    k_zero<<<256, 256>>>();
    k_init<<<B, 256>>>(xyz, osc);
    for (int it = 0; it < ITERS; ++it)
        k_iter<<<NB, 256>>>(xyz, osc, ogam, it);
    k_fin<<<B, K>>>(opi, oxyz);
    dim3 gg(GEMM_CH, B);
    k_nf<<<gg, 128>>>(feats, ogam);
    k_nf_fin<<<256, 256>>>(onf);
}

// round 11
// speedup vs baseline: 1.5750x; 1.4097x over previous
#include <cuda_runtime.h>
#include <cstdint>
#include <cstddef>

static constexpr int   B      = 8;
static constexpr int   N      = 32768;
static constexpr int   K      = 128;
static constexpr int   D      = 64;
static constexpr int   ITERS  = 10;
static constexpr float EPS    = 1e-8f;
static constexpr float LOG2E  = 1.4426950408889634f;

static constexpr int BPB   = 32;          // blocks per batch (grid 256: best measured config)
static constexpr int NB    = B * BPB;     // 256 blocks
static constexpr int CHUNK = N / BPB;     // 1024 points per block = 4 aligned tiles
static constexpr int TILE  = 256;         // points staged to smem per tile

static constexpr int GEMM_CH = 64;        // n-chunks per batch for node_feats GEMM -> 512 blocks
static constexpr int TN      = 32;        // points per GEMM smem tile
static constexpr int FPAD    = 4;         // s_f row padding (keeps float4 alignment)

typedef unsigned long long u64;

// ---------------- device scratch (no allocations allowed) ----------------
__device__ float g_buf[ITERS][B][K][4];   // per-iter accumulators: denom, Mx, My, Mz
__device__ float g_cinit[B][K][3];
__device__ float g_ssum[B];
__device__ float g_nfacc[B * K * D];

// ---------------- small asm helpers ----------------
__device__ __forceinline__ float ex2f(float x) {
    float r; asm("ex2.approx.ftz.f32 %0, %1;" : "=f"(r) : "f"(x)); return r;
}
__device__ __forceinline__ u64 pack2(float lo, float hi) {
    u64 r; asm("mov.b64 %0, {%1, %2};" : "=l"(r) : "f"(lo), "f"(hi)); return r;
}
__device__ __forceinline__ void unpack2(u64 v, float& lo, float& hi) {
    asm("mov.b64 {%0, %1}, %2;" : "=f"(lo), "=f"(hi) : "l"(v));
}
__device__ __forceinline__ void ffma2(u64& d, u64 a, u64 b) {
    asm("fma.rn.f32x2 %0, %1, %2, %0;" : "+l"(d) : "l"(a), "l"(b));
}

// ---------------- kernel 1: zero scratch ----------------
__global__ void k_zero() {
    int i = blockIdx.x * blockDim.x + threadIdx.x;   // launched with 65536 threads
    float* gb = &g_buf[0][0][0][0];
    if (i < ITERS * B * K * 4) gb[i] = 0.f;
    if (i < B * K * D)         g_nfacc[i] = 0.f;
}

// ---------------- kernel 2: init centers + per-batch score sums ----------------
__global__ void k_init(const float* __restrict__ xyz, const float* __restrict__ osc) {
    int b = blockIdx.x, tid = threadIdx.x;
    __shared__ float red[256];
    const float* w = osc + (size_t)b * N;
    float s = 0.f;
    for (int n = tid; n < N; n += 256) s += w[n];
    red[tid] = s;
    __syncthreads();
    for (int st = 128; st > 0; st >>= 1) {
        if (tid < st) red[tid] += red[tid + st];
        __syncthreads();
    }
    if (tid == 0) g_ssum[b] = red[0] + EPS;
    if (tid < K) {
        int n0 = tid * (N / K);
        const float* xb = xyz + (size_t)b * 3 * N;
        g_cinit[b][tid][0] = xb[n0];
        g_cinit[b][tid][1] = xb[N + n0];
        g_cinit[b][tid][2] = xb[2 * N + n0];
    }
}

// ---------------- kernel 3: one clustering iteration (launched ITERS times) ----------------
// Two-pass softmax: pass1 point-per-thread denominators (no shuffles),
// pass2 cluster-per-lane accumulation (no reduction, no divide in hot path).
__global__ void __launch_bounds__(256, 2)
k_iter(const float* __restrict__ xyz, const float* __restrict__ osc,
       float* __restrict__ out_gamma, int it) {
    const int b    = blockIdx.x / BPB;
    const int slot = blockIdx.x % BPB;
    const int cs   = slot * CHUNK;
    const int tid  = threadIdx.x;
    const int lane = tid & 31;
    const int wid  = tid >> 5;

    __shared__ float4 s_A[K];       // center constants (2*log2e*c, -log2e*|c|^2)
    __shared__ float4 s_pt[TILE];   // staged points: x0,x1,x2,w
    __shared__ float  s_v[TILE];    // per-point w/s (softmax scale)

    const float* x0p = xyz + (size_t)b * 3 * N;
    const float* x1p = x0p + N;
    const float* x2p = x0p + 2 * N;
    const float* wp  = osc + (size_t)b * N;

    // -- derive A_k from current centers --
    if (tid < K) {
        float c0, c1, c2;
        if (it == 0) {
            c0 = g_cinit[b][tid][0];
            c1 = g_cinit[b][tid][1];
            c2 = g_cinit[b][tid][2];
        } else {
            const float* pb = &g_buf[it - 1][b][tid][0];
            float inv = 1.0f / (pb[0] + EPS);
            c0 = pb[1] * inv; c1 = pb[2] * inv; c2 = pb[3] * inv;
        }
        s_A[tid] = make_float4(2.f * LOG2E * c0, 2.f * LOG2E * c1, 2.f * LOG2E * c2,
                               -LOG2E * (c0 * c0 + c1 * c1 + c2 * c2));
    }
    __syncthreads();

    // each lane owns 4 consecutive clusters (pass 2)
    const float4 A0 = s_A[lane * 4 + 0];
    const float4 A1 = s_A[lane * 4 + 1];
    const float4 A2 = s_A[lane * 4 + 2];
    const float4 A3 = s_A[lane * 4 + 3];

    float aD0 = 0.f, aD1 = 0.f, aD2 = 0.f, aD3 = 0.f;
    float aX0 = 0.f, aX1 = 0.f, aX2 = 0.f, aX3 = 0.f;
    float aY0 = 0.f, aY1 = 0.f, aY2 = 0.f, aY3 = 0.f;
    float aZ0 = 0.f, aZ1 = 0.f, aZ2 = 0.f, aZ3 = 0.f;

    const bool fin = (it == ITERS - 1);

    #pragma unroll
    for (int t4 = 0; t4 < CHUNK / TILE; ++t4) {
        const int tb = cs + t4 * TILE;
        const int gi = tb + tid;
        float4 pd;
        pd.x = x0p[gi]; pd.y = x1p[gi]; pd.z = x2p[gi]; pd.w = wp[gi];
        __syncthreads();            // previous tile fully consumed
        s_pt[tid] = pd;

        // ---- pass 1: own point's softmax denominator (no cross-lane ops) ----
        {
            float s0 = 0.f, s1 = 0.f, s2 = 0.f, s3 = 0.f;
            #pragma unroll 4
            for (int k = 0; k < K; k += 4) {
                float4 a = s_A[k + 0];
                float4 bb = s_A[k + 1];
                float4 c = s_A[k + 2];
                float4 d = s_A[k + 3];
                float t0 = fmaf(a.x,  pd.x, a.w);  t0 = fmaf(a.y,  pd.y, t0); t0 = fmaf(a.z,  pd.z, t0);
                float t1 = fmaf(bb.x, pd.x, bb.w); t1 = fmaf(bb.y, pd.y, t1); t1 = fmaf(bb.z, pd.z, t1);
                float t2 = fmaf(c.x,  pd.x, c.w);  t2 = fmaf(c.y,  pd.y, t2); t2 = fmaf(c.z,  pd.z, t2);
                float t3 = fmaf(d.x,  pd.x, d.w);  t3 = fmaf(d.y,  pd.y, t3); t3 = fmaf(d.z,  pd.z, t3);
                s0 += ex2f(t0); s1 += ex2f(t1); s2 += ex2f(t2); s3 += ex2f(t3);
            }
            s_v[tid] = __fdividef(pd.w, (s0 + s1) + (s2 + s3));
        }
        __syncthreads();            // tile points + v ready

        // ---- pass 2: cluster-per-lane accumulation ----
        #pragma unroll 8
        for (int m = 0; m < 32; ++m) {
            const int p = wid + m * 8;
            const float4 P = s_pt[p];
            const float  v = s_v[p];

            float t0 = fmaf(A0.x, P.x, A0.w); t0 = fmaf(A0.y, P.y, t0); t0 = fmaf(A0.z, P.z, t0);
            float t1 = fmaf(A1.x, P.x, A1.w); t1 = fmaf(A1.y, P.y, t1); t1 = fmaf(A1.z, P.z, t1);
            float t2 = fmaf(A2.x, P.x, A2.w); t2 = fmaf(A2.y, P.y, t2); t2 = fmaf(A2.z, P.z, t2);
            float t3 = fmaf(A3.x, P.x, A3.w); t3 = fmaf(A3.y, P.y, t3); t3 = fmaf(A3.z, P.z, t3);

            float g0 = ex2f(t0) * v, g1 = ex2f(t1) * v;
            float g2 = ex2f(t2) * v, g3 = ex2f(t3) * v;

            aD0 += g0; aX0 = fmaf(g0, P.x, aX0); aY0 = fmaf(g0, P.y, aY0); aZ0 = fmaf(g0, P.z, aZ0);
            aD1 += g1; aX1 = fmaf(g1, P.x, aX1); aY1 = fmaf(g1, P.y, aY1); aZ1 = fmaf(g1, P.z, aZ1);
            aD2 += g2; aX2 = fmaf(g2, P.x, aX2); aY2 = fmaf(g2, P.y, aY2); aZ2 = fmaf(g2, P.z, aZ2);
            aD3 += g3; aX3 = fmaf(g3, P.x, aX3); aY3 = fmaf(g3, P.y, aY3); aZ3 = fmaf(g3, P.z, aZ3);

            if (fin) {
                *(float4*)&out_gamma[((size_t)(b * N + tb + p)) * K + lane * 4]
                    = make_float4(g0, g1, g2, g3);
            }
        }
    }

    // -- flush register accumulators to global --
    float* pb = &g_buf[it][b][lane * 4][0];
    atomicAdd(pb + 0,  aD0); atomicAdd(pb + 1,  aX0); atomicAdd(pb + 2,  aY0); atomicAdd(pb + 3,  aZ0);
    atomicAdd(pb + 4,  aD1); atomicAdd(pb + 5,  aX1); atomicAdd(pb + 6,  aY1); atomicAdd(pb + 7,  aZ1);
    atomicAdd(pb + 8,  aD2); atomicAdd(pb + 9,  aX2); atomicAdd(pb + 10, aY2); atomicAdd(pb + 11, aZ2);
    atomicAdd(pb + 12, aD3); atomicAdd(pb + 13, aX3); atomicAdd(pb + 14, aY3); atomicAdd(pb + 15, aZ3);
}

// ---------------- kernel 4: finalize pi / node_xyz ----------------
__global__ void k_fin(float* __restrict__ out_pi, float* __restrict__ out_nxyz) {
    int b = blockIdx.x, k = threadIdx.x;   // <<<B, K>>>
    const float* pb = &g_buf[ITERS - 1][b][k][0];
    float raw = pb[0];
    float inv = 1.0f / (raw + EPS);
    out_pi[b * K + k] = raw / g_ssum[b];
    out_nxyz[(b * K + k) * 3 + 0] = pb[1] * inv;
    out_nxyz[(b * K + k) * 3 + 1] = pb[2] * inv;
    out_nxyz[(b * K + k) * 3 + 2] = pb[3] * inv;
}

// ---------------- kernel 5: node_feats = gamma^T @ feats (split-N, f32x2 FMA) ----------------
__global__ void __launch_bounds__(128)
k_nf(const float* __restrict__ feats, const float* __restrict__ gamma) {
    const int b  = blockIdx.y;
    const int n0 = blockIdx.x * (N / GEMM_CH);
    const int tid = threadIdx.x;
    const int k0 = (tid >> 3) * 8;   // 16 k-groups of 8
    const int d0 = (tid & 7) * 8;    // 8 d-groups of 8

    __shared__ float s_g[TN][K];          // 16 KB
    __shared__ float s_f[TN][D + FPAD];   // padded by 4 -> float4-aligned rows

    u64 acc[8][4];
    #pragma unroll
    for (int i = 0; i < 8; i++)
        #pragma unroll
        for (int c = 0; c < 4; c++) acc[i][c] = pack2(0.f, 0.f);

    const float* gbase = gamma + (size_t)b * N * K;
    const float* fbase = feats + (size_t)b * D * N;

    for (int t0 = n0; t0 < n0 + N / GEMM_CH; t0 += TN) {
        __syncthreads();
        {   // gamma tile: TN*K floats = 1024 float4, 8 per thread, coalesced
            const float4* src = (const float4*)(gbase + (size_t)t0 * K);
            float4* dst = (float4*)&s_g[0][0];
            #pragma unroll
            for (int j = 0; j < 8; j++) dst[tid + j * 128] = src[tid + j * 128];
        }
        {   // feats tile: D rows of TN consecutive n, transposed into s_f[n][d]
            #pragma unroll
            for (int j = 0; j < 16; j++) {
                int li = tid + j * 128;          // 0..2047
                int d = li >> 5, i = li & 31;
                s_f[i][d] = fbase[(size_t)d * N + t0 + i];
            }
        }
        __syncthreads();

        for (int i = 0; i < TN; i++) {
            float4 ga  = *(const float4*)&s_g[i][k0];
            float4 gb2 = *(const float4*)&s_g[i][k0 + 4];
            float4 fa  = *(const float4*)&s_f[i][d0];
            float4 fb  = *(const float4*)&s_f[i][d0 + 4];
            u64 f01 = pack2(fa.x, fa.y), f23 = pack2(fa.z, fa.w);
            u64 f45 = pack2(fb.x, fb.y), f67 = pack2(fb.z, fb.w);
            float gk[8] = {ga.x, ga.y, ga.z, ga.w, gb2.x, gb2.y, gb2.z, gb2.w};
            #pragma unroll
            for (int kk = 0; kk < 8; kk++) {
                u64 gg = pack2(gk[kk], gk[kk]);
                ffma2(acc[kk][0], gg, f01);
                ffma2(acc[kk][1], gg, f23);
                ffma2(acc[kk][2], gg, f45);
                ffma2(acc[kk][3], gg, f67);
            }
        }
    }

    #pragma unroll
    for (int kk = 0; kk < 8; kk++)
        #pragma unroll
        for (int c = 0; c < 4; c++) {
            float lo, hi; unpack2(acc[kk][c], lo, hi);
            float* dst = &g_nfacc[((size_t)b * K + (k0 + kk)) * D + d0 + c * 2];
            atomicAdd(dst, lo);
            atomicAdd(dst + 1, hi);
        }
}

// ---------------- kernel 6: divide node_feats by denom ----------------
__global__ void k_nf_fin(float* __restrict__ out_nf) {
    int i = blockIdx.x * blockDim.x + threadIdx.x;   // 65536 threads
    if (i < B * K * D) {
        int b = i / (K * D);
        int k = (i % (K * D)) / D;
        float dn = g_buf[ITERS - 1][b][k][0] + EPS;
        out_nf[i] = g_nfacc[i] / dn;
    }
}

// ---------------- launch ----------------
extern "C" void kernel_launch(void* const* d_in, const int* in_sizes, int n_in,
                              void* d_out, int out_size) {
    const float* xyz   = (const float*)d_in[0];
    const float* feats = (const float*)d_in[1];
    const float* osc   = (const float*)d_in[2];

    float* out   = (float*)d_out;
    float* ogam  = out;
    float* opi   = ogam + (size_t)B * N * K;
    float* oxyz  = opi + B * K;
    float* onf   = oxyz + B * K * 3;

    k_zero<<<256, 256>>>();
    k_init<<<B, 256>>>(xyz, osc);
    for (int it = 0; it < ITERS; ++it)
        k_iter<<<NB, 256>>>(xyz, osc, ogam, it);
    k_fin<<<B, K>>>(opi, oxyz);
    dim3 gg(GEMM_CH, B);
    k_nf<<<gg, 128>>>(feats, ogam);
    k_nf_fin<<<256, 256>>>(onf);
}

// round 12
// speedup vs baseline: 2.6360x; 1.6737x over previous
#include <cuda_runtime.h>
#include <cstdint>
#include <cstddef>

static constexpr int   B      = 8;
static constexpr int   N      = 32768;
static constexpr int   K      = 128;
static constexpr int   D      = 64;
static constexpr int   ITERS  = 10;
static constexpr float EPS    = 1e-8f;
static constexpr float LOG2E  = 1.4426950408889634f;

static constexpr int BPB   = 64;          // blocks per batch -> grid 512, CHUNK aligned
static constexpr int NB    = B * BPB;     // 512 blocks
static constexpr int CHUNK = N / BPB;     // 512 points per block = 2 aligned tiles
static constexpr int TILE  = 256;         // points staged to smem per tile

static constexpr int GEMM_CH = 64;        // n-chunks per batch for node_feats GEMM -> 512 blocks
static constexpr int TN      = 32;        // points per GEMM smem tile
static constexpr int FPAD    = 4;         // s_f row padding (keeps float4 alignment)

typedef unsigned long long u64;

// ---------------- device scratch (no allocations allowed) ----------------
__device__ float g_buf[ITERS][B][K][4];   // per-iter accumulators: denom, Mx, My, Mz
__device__ float g_cinit[B][K][3];
__device__ float g_ssum[B];
__device__ float g_nfacc[B * K * D];

// ---------------- small asm helpers ----------------
__device__ __forceinline__ float ex2f(float x) {
    float r; asm("ex2.approx.ftz.f32 %0, %1;" : "=f"(r) : "f"(x)); return r;
}
__device__ __forceinline__ u64 pack2(float lo, float hi) {
    u64 r; asm("mov.b64 %0, {%1, %2};" : "=l"(r) : "f"(lo), "f"(hi)); return r;
}
__device__ __forceinline__ void unpack2(u64 v, float& lo, float& hi) {
    asm("mov.b64 {%0, %1}, %2;" : "=f"(lo), "=f"(hi) : "l"(v));
}
__device__ __forceinline__ void ffma2(u64& d, u64 a, u64 b) {
    asm("fma.rn.f32x2 %0, %1, %2, %0;" : "+l"(d) : "l"(a), "l"(b));
}

// ---------------- kernel 1: zero scratch ----------------
__global__ void k_zero() {
    int i = blockIdx.x * blockDim.x + threadIdx.x;   // launched with 65536 threads
    float* gb = &g_buf[0][0][0][0];
    if (i < ITERS * B * K * 4) gb[i] = 0.f;
    if (i < B * K * D)         g_nfacc[i] = 0.f;
}

// ---------------- kernel 2: init centers + per-batch score sums ----------------
__global__ void k_init(const float* __restrict__ xyz, const float* __restrict__ osc) {
    int b = blockIdx.x, tid = threadIdx.x;
    __shared__ float red[256];
    const float* w = osc + (size_t)b * N;
    float s = 0.f;
    for (int n = tid; n < N; n += 256) s += w[n];
    red[tid] = s;
    __syncthreads();
    for (int st = 128; st > 0; st >>= 1) {
        if (tid < st) red[tid] += red[tid + st];
        __syncthreads();
    }
    if (tid == 0) g_ssum[b] = red[0] + EPS;
    if (tid < K) {
        int n0 = tid * (N / K);
        const float* xb = xyz + (size_t)b * 3 * N;
        g_cinit[b][tid][0] = xb[n0];
        g_cinit[b][tid][1] = xb[N + n0];
        g_cinit[b][tid][2] = xb[2 * N + n0];
    }
}

// ---------------- kernel 3: one clustering iteration (launched ITERS times) ----------------
// Two-pass softmax (pass1: per-point denominator, pass2: cluster-per-lane accumulation).
// Clean aligned chunks (no guards); block-level smem moment reduction before global atomics.
__global__ void __launch_bounds__(256, 3)
k_iter(const float* __restrict__ xyz, const float* __restrict__ osc,
       float* __restrict__ out_gamma, int it) {
    const int b    = blockIdx.x >> 6;         // / BPB (=64)
    const int slot = blockIdx.x & (BPB - 1);
    const int cs   = slot * CHUNK;
    const int tid  = threadIdx.x;
    const int lane = tid & 31;
    const int wid  = tid >> 5;

    __shared__ float4 s_A[K];          // center constants (2*log2e*c, -log2e*|c|^2)
    __shared__ float4 s_pt[TILE];      // staged points: x0,x1,x2,w
    __shared__ float  s_v[TILE];       // per-point w/s (softmax scale)
    __shared__ float  s_mom[32 * 17];  // block moment reduction, stride-17 (conflict-free)

    const float* x0p = xyz + (size_t)b * 3 * N;
    const float* x1p = x0p + N;
    const float* x2p = x0p + 2 * N;
    const float* wp  = osc + (size_t)b * N;

    // -- zero moment scratch + derive A_k from current centers --
    s_mom[tid] = 0.f;
    s_mom[tid + 256] = 0.f;
    if (tid < 32) s_mom[tid + 512] = 0.f;
    if (tid < K) {
        float c0, c1, c2;
        if (it == 0) {
            c0 = g_cinit[b][tid][0];
            c1 = g_cinit[b][tid][1];
            c2 = g_cinit[b][tid][2];
        } else {
            const float* pb = &g_buf[it - 1][b][tid][0];
            float inv = 1.0f / (pb[0] + EPS);
            c0 = pb[1] * inv; c1 = pb[2] * inv; c2 = pb[3] * inv;
        }
        s_A[tid] = make_float4(2.f * LOG2E * c0, 2.f * LOG2E * c1, 2.f * LOG2E * c2,
                               -LOG2E * (c0 * c0 + c1 * c1 + c2 * c2));
    }
    __syncthreads();

    // each lane owns 4 consecutive clusters (pass 2)
    const float4 A0 = s_A[lane * 4 + 0];
    const float4 A1 = s_A[lane * 4 + 1];
    const float4 A2 = s_A[lane * 4 + 2];
    const float4 A3 = s_A[lane * 4 + 3];

    float aD0 = 0.f, aD1 = 0.f, aD2 = 0.f, aD3 = 0.f;
    float aX0 = 0.f, aX1 = 0.f, aX2 = 0.f, aX3 = 0.f;
    float aY0 = 0.f, aY1 = 0.f, aY2 = 0.f, aY3 = 0.f;
    float aZ0 = 0.f, aZ1 = 0.f, aZ2 = 0.f, aZ3 = 0.f;

    const bool fin = (it == ITERS - 1);

    #pragma unroll
    for (int t4 = 0; t4 < CHUNK / TILE; ++t4) {
        const int tb = cs + t4 * TILE;
        const int gi = tb + tid;
        float4 pd;
        pd.x = x0p[gi]; pd.y = x1p[gi]; pd.z = x2p[gi]; pd.w = wp[gi];
        __syncthreads();            // previous tile fully consumed
        s_pt[tid] = pd;

        // ---- pass 1: own point's softmax denominator (no cross-lane ops) ----
        {
            float s0 = 0.f, s1 = 0.f, s2 = 0.f, s3 = 0.f;
            #pragma unroll 2
            for (int k = 0; k < K; k += 4) {
                float4 a = s_A[k + 0];
                float4 bb = s_A[k + 1];
                float4 c = s_A[k + 2];
                float4 d = s_A[k + 3];
                float t0 = fmaf(a.x,  pd.x, a.w);  t0 = fmaf(a.y,  pd.y, t0); t0 = fmaf(a.z,  pd.z, t0);
                float t1 = fmaf(bb.x, pd.x, bb.w); t1 = fmaf(bb.y, pd.y, t1); t1 = fmaf(bb.z, pd.z, t1);
                float t2 = fmaf(c.x,  pd.x, c.w);  t2 = fmaf(c.y,  pd.y, t2); t2 = fmaf(c.z,  pd.z, t2);
                float t3 = fmaf(d.x,  pd.x, d.w);  t3 = fmaf(d.y,  pd.y, t3); t3 = fmaf(d.z,  pd.z, t3);
                s0 += ex2f(t0); s1 += ex2f(t1); s2 += ex2f(t2); s3 += ex2f(t3);
            }
            s_v[tid] = __fdividef(pd.w, (s0 + s1) + (s2 + s3));
        }
        __syncthreads();            // tile points + v ready

        // ---- pass 2: cluster-per-lane accumulation ----
        #pragma unroll 8
        for (int m = 0; m < 32; ++m) {
            const int p = wid + m * 8;
            const float4 P = s_pt[p];
            const float  v = s_v[p];

            float t0 = fmaf(A0.x, P.x, A0.w); t0 = fmaf(A0.y, P.y, t0); t0 = fmaf(A0.z, P.z, t0);
            float t1 = fmaf(A1.x, P.x, A1.w); t1 = fmaf(A1.y, P.y, t1); t1 = fmaf(A1.z, P.z, t1);
            float t2 = fmaf(A2.x, P.x, A2.w); t2 = fmaf(A2.y, P.y, t2); t2 = fmaf(A2.z, P.z, t2);
            float t3 = fmaf(A3.x, P.x, A3.w); t3 = fmaf(A3.y, P.y, t3); t3 = fmaf(A3.z, P.z, t3);

            float g0 = ex2f(t0) * v, g1 = ex2f(t1) * v;
            float g2 = ex2f(t2) * v, g3 = ex2f(t3) * v;

            aD0 += g0; aX0 = fmaf(g0, P.x, aX0); aY0 = fmaf(g0, P.y, aY0); aZ0 = fmaf(g0, P.z, aZ0);
            aD1 += g1; aX1 = fmaf(g1, P.x, aX1); aY1 = fmaf(g1, P.y, aY1); aZ1 = fmaf(g1, P.z, aZ1);
            aD2 += g2; aX2 = fmaf(g2, P.x, aX2); aY2 = fmaf(g2, P.y, aY2); aZ2 = fmaf(g2, P.z, aZ2);
            aD3 += g3; aX3 = fmaf(g3, P.x, aX3); aY3 = fmaf(g3, P.y, aY3); aZ3 = fmaf(g3, P.z, aZ3);

            if (fin) {
                *(float4*)&out_gamma[((size_t)(b * N + tb + p)) * K + lane * 4]
                    = make_float4(g0, g1, g2, g3);
            }
        }
    }

    // -- block-level smem reduction of moments (stride-17 layout: lane*17 + j*4 + c) --
    {
        float* sm = &s_mom[lane * 17];
        atomicAdd(sm + 0,  aD0); atomicAdd(sm + 1,  aX0); atomicAdd(sm + 2,  aY0); atomicAdd(sm + 3,  aZ0);
        atomicAdd(sm + 4,  aD1); atomicAdd(sm + 5,  aX1); atomicAdd(sm + 6,  aY1); atomicAdd(sm + 7,  aZ1);
        atomicAdd(sm + 8,  aD2); atomicAdd(sm + 9,  aX2); atomicAdd(sm + 10, aY2); atomicAdd(sm + 11, aZ2);
        atomicAdd(sm + 12, aD3); atomicAdd(sm + 13, aX3); atomicAdd(sm + 14, aY3); atomicAdd(sm + 15, aZ3);
    }
    __syncthreads();

    // -- flush: one global atomic per (k,comp) per block; 2 per thread --
    {
        float* pb = &g_buf[it][b][0][0];
        #pragma unroll
        for (int r = 0; r < 2; ++r) {
            int t = tid + r * 256;                 // 0..511 = lane_src*16 + idx
            float val = s_mom[(t >> 4) * 17 + (t & 15)];
            atomicAdd(pb + t, val);                // global offset = (t>>4)*16 + (t&15) = t
        }
    }
}

// ---------------- kernel 4: finalize pi / node_xyz ----------------
__global__ void k_fin(float* __restrict__ out_pi, float* __restrict__ out_nxyz) {
    int b = blockIdx.x, k = threadIdx.x;   // <<<B, K>>>
    const float* pb = &g_buf[ITERS - 1][b][k][0];
    float raw = pb[0];
    float inv = 1.0f / (raw + EPS);
    out_pi[b * K + k] = raw / g_ssum[b];
    out_nxyz[(b * K + k) * 3 + 0] = pb[1] * inv;
    out_nxyz[(b * K + k) * 3 + 1] = pb[2] * inv;
    out_nxyz[(b * K + k) * 3 + 2] = pb[3] * inv;
}

// ---------------- kernel 5: node_feats = gamma^T @ feats (split-N, f32x2 FMA) ----------------
__global__ void __launch_bounds__(128)
k_nf(const float* __restrict__ feats, const float* __restrict__ gamma) {
    const int b  = blockIdx.y;
    const int n0 = blockIdx.x * (N / GEMM_CH);
    const int tid = threadIdx.x;
    const int k0 = (tid >> 3) * 8;   // 16 k-groups of 8
    const int d0 = (tid & 7) * 8;    // 8 d-groups of 8

    __shared__ float s_g[TN][K];          // 16 KB
    __shared__ float s_f[TN][D + FPAD];   // padded by 4 -> float4-aligned rows

    u64 acc[8][4];
    #pragma unroll
    for (int i = 0; i < 8; i++)
        #pragma unroll
        for (int c = 0; c < 4; c++) acc[i][c] = pack2(0.f, 0.f);

    const float* gbase = gamma + (size_t)b * N * K;
    const float* fbase = feats + (size_t)b * D * N;

    for (int t0 = n0; t0 < n0 + N / GEMM_CH; t0 += TN) {
        __syncthreads();
        {   // gamma tile: TN*K floats = 1024 float4, 8 per thread, coalesced
            const float4* src = (const float4*)(gbase + (size_t)t0 * K);
            float4* dst = (float4*)&s_g[0][0];
            #pragma unroll
            for (int j = 0; j < 8; j++) dst[tid + j * 128] = src[tid + j * 128];
        }
        {   // feats tile: D rows of TN consecutive n, transposed into s_f[n][d]
            #pragma unroll
            for (int j = 0; j < 16; j++) {
                int li = tid + j * 128;          // 0..2047
                int d = li >> 5, i = li & 31;
                s_f[i][d] = fbase[(size_t)d * N + t0 + i];
            }
        }
        __syncthreads();

        for (int i = 0; i < TN; i++) {
            float4 ga  = *(const float4*)&s_g[i][k0];
            float4 gb2 = *(const float4*)&s_g[i][k0 + 4];
            float4 fa  = *(const float4*)&s_f[i][d0];
            float4 fb  = *(const float4*)&s_f[i][d0 + 4];
            u64 f01 = pack2(fa.x, fa.y), f23 = pack2(fa.z, fa.w);
            u64 f45 = pack2(fb.x, fb.y), f67 = pack2(fb.z, fb.w);
            float gk[8] = {ga.x, ga.y, ga.z, ga.w, gb2.x, gb2.y, gb2.z, gb2.w};
            #pragma unroll
            for (int kk = 0; kk < 8; kk++) {
                u64 gg = pack2(gk[kk], gk[kk]);
                ffma2(acc[kk][0], gg, f01);
                ffma2(acc[kk][1], gg, f23);
                ffma2(acc[kk][2], gg, f45);
                ffma2(acc[kk][3], gg, f67);
            }
        }
    }

    #pragma unroll
    for (int kk = 0; kk < 8; kk++)
        #pragma unroll
        for (int c = 0; c < 4; c++) {
            float lo, hi; unpack2(acc[kk][c], lo, hi);
            float* dst = &g_nfacc[((size_t)b * K + (k0 + kk)) * D + d0 + c * 2];
            atomicAdd(dst, lo);
            atomicAdd(dst + 1, hi);
        }
}

// ---------------- kernel 6: divide node_feats by denom ----------------
__global__ void k_nf_fin(float* __restrict__ out_nf) {
    int i = blockIdx.x * blockDim.x + threadIdx.x;   // 65536 threads
    if (i < B * K * D) {
        int b = i / (K * D);
        int k = (i % (K * D)) / D;
        float dn = g_buf[ITERS - 1][b][k][0] + EPS;
        out_nf[i] = g_nfacc[i] / dn;
    }
}

// ---------------- launch ----------------
extern "C" void kernel_launch(void* const* d_in, const int* in_sizes, int n_in,
                              void* d_out, int out_size) {
    const float* xyz   = (const float*)d_in[0];
    const float* feats = (const float*)d_in[1];
    const float* osc   = (const float*)d_in[2];

    float* out   = (float*)d_out;
    float* ogam  = out;
    float* opi   = ogam + (size_t)B * N * K;
    float* oxyz  = opi + B * K;
    float* onf   = oxyz + B * K * 3;

    k_zero<<<256, 256>>>();
    k_init<<<B, 256>>>(xyz, osc);
    for (int it = 0; it < ITERS; ++it)
        k_iter<<<NB, 256>>>(xyz, osc, ogam, it);
    k_fin<<<B, K>>>(opi, oxyz);
    dim3 gg(GEMM_CH, B);
    k_nf<<<gg, 128>>>(feats, ogam);
    k_nf_fin<<<256, 256>>>(onf);
}

// round 14
// speedup vs baseline: 2.6382x; 1.0008x over previous
#include <cuda_runtime.h>
#include <cstdint>
#include <cstddef>

static constexpr int   B      = 8;
static constexpr int   N      = 32768;
static constexpr int   K      = 128;
static constexpr int   D      = 64;
static constexpr int   ITERS  = 10;
static constexpr float EPS    = 1e-8f;
static constexpr float LOG2E  = 1.4426950408889634f;

static constexpr int BPB   = 64;          // blocks per batch -> grid 512, CHUNK aligned
static constexpr int NB    = B * BPB;     // 512 blocks
static constexpr int CHUNK = N / BPB;     // 512 points per block = 2 aligned tiles
static constexpr int TILE  = 256;         // points staged to smem per tile

static constexpr int GEMM_CH = 64;        // n-chunks per batch for node_feats GEMM -> 512 blocks
static constexpr int TN      = 32;        // points per GEMM smem tile
static constexpr int FPAD    = 4;         // s_f row padding (keeps float4 alignment)

typedef unsigned long long u64;

// ---------------- device scratch (no allocations allowed) ----------------
__device__ float g_buf[ITERS][B][K][4];   // per-iter accumulators: denom, Mx, My, Mz
__device__ float g_cinit[B][K][3];
__device__ float g_ssum[B];
__device__ float g_nfacc[B * K * D];

// ---------------- small asm helpers ----------------
__device__ __forceinline__ float ex2f(float x) {
    float r; asm("ex2.approx.ftz.f32 %0, %1;" : "=f"(r) : "f"(x)); return r;
}
__device__ __forceinline__ u64 pack2(float lo, float hi) {
    u64 r; asm("mov.b64 %0, {%1, %2};" : "=l"(r) : "f"(lo), "f"(hi)); return r;
}
__device__ __forceinline__ void unpack2(u64 v, float& lo, float& hi) {
    asm("mov.b64 {%0, %1}, %2;" : "=f"(lo), "=f"(hi) : "l"(v));
}
__device__ __forceinline__ void ffma2(u64& d, u64 a, u64 b) {
    asm("fma.rn.f32x2 %0, %1, %2, %0;" : "+l"(d) : "l"(a), "l"(b));
}

// ---------------- kernel 1: zero scratch ----------------
__global__ void k_zero() {
    int i = blockIdx.x * blockDim.x + threadIdx.x;   // launched with 65536 threads
    float* gb = &g_buf[0][0][0][0];
    if (i < ITERS * B * K * 4) gb[i] = 0.f;
    if (i < B * K * D)         g_nfacc[i] = 0.f;
}

// ---------------- kernel 2: init centers + per-batch score sums ----------------
__global__ void k_init(const float* __restrict__ xyz, const float* __restrict__ osc) {
    int b = blockIdx.x, tid = threadIdx.x;
    __shared__ float red[256];
    const float* w = osc + (size_t)b * N;
    float s = 0.f;
    for (int n = tid; n < N; n += 256) s += w[n];
    red[tid] = s;
    __syncthreads();
    for (int st = 128; st > 0; st >>= 1) {
        if (tid < st) red[tid] += red[tid + st];
        __syncthreads();
    }
    if (tid == 0) g_ssum[b] = red[0] + EPS;
    if (tid < K) {
        int n0 = tid * (N / K);
        const float* xb = xyz + (size_t)b * 3 * N;
        g_cinit[b][tid][0] = xb[n0];
        g_cinit[b][tid][1] = xb[N + n0];
        g_cinit[b][tid][2] = xb[2 * N + n0];
    }
}

// ---------------- kernel 3: one clustering iteration (launched ITERS times) ----------------
// Two-pass softmax (pass1: per-point denominator, pass2: cluster-per-lane accumulation).
// Clean aligned chunks (no guards); block-level smem moment reduction before global atomics.
__global__ void __launch_bounds__(256, 3)
k_iter(const float* __restrict__ xyz, const float* __restrict__ osc,
       float* __restrict__ out_gamma, int it) {
    const int b    = blockIdx.x >> 6;         // / BPB (=64)
    const int slot = blockIdx.x & (BPB - 1);
    const int cs   = slot * CHUNK;
    const int tid  = threadIdx.x;
    const int lane = tid & 31;
    const int wid  = tid >> 5;

    __shared__ float4 s_A[K];          // center constants (2*log2e*c, -log2e*|c|^2)
    __shared__ float4 s_pt[TILE];      // staged points: x0,x1,x2,w
    __shared__ float  s_v[TILE];       // per-point w/s (softmax scale)
    __shared__ float  s_mom[32 * 17];  // block moment reduction, stride-17 (conflict-free)

    const float* x0p = xyz + (size_t)b * 3 * N;
    const float* x1p = x0p + N;
    const float* x2p = x0p + 2 * N;
    const float* wp  = osc + (size_t)b * N;

    // -- zero moment scratch + derive A_k from current centers --
    s_mom[tid] = 0.f;
    s_mom[tid + 256] = 0.f;
    if (tid < 32) s_mom[tid + 512] = 0.f;
    if (tid < K) {
        float c0, c1, c2;
        if (it == 0) {
            c0 = g_cinit[b][tid][0];
            c1 = g_cinit[b][tid][1];
            c2 = g_cinit[b][tid][2];
        } else {
            const float* pb = &g_buf[it - 1][b][tid][0];
            float inv = 1.0f / (pb[0] + EPS);
            c0 = pb[1] * inv; c1 = pb[2] * inv; c2 = pb[3] * inv;
        }
        s_A[tid] = make_float4(2.f * LOG2E * c0, 2.f * LOG2E * c1, 2.f * LOG2E * c2,
                               -LOG2E * (c0 * c0 + c1 * c1 + c2 * c2));
    }
    __syncthreads();

    // each lane owns 4 consecutive clusters (pass 2)
    const float4 A0 = s_A[lane * 4 + 0];
    const float4 A1 = s_A[lane * 4 + 1];
    const float4 A2 = s_A[lane * 4 + 2];
    const float4 A3 = s_A[lane * 4 + 3];

    float aD0 = 0.f, aD1 = 0.f, aD2 = 0.f, aD3 = 0.f;
    float aX0 = 0.f, aX1 = 0.f, aX2 = 0.f, aX3 = 0.f;
    float aY0 = 0.f, aY1 = 0.f, aY2 = 0.f, aY3 = 0.f;
    float aZ0 = 0.f, aZ1 = 0.f, aZ2 = 0.f, aZ3 = 0.f;

    const bool fin = (it == ITERS - 1);

    #pragma unroll
    for (int t4 = 0; t4 < CHUNK / TILE; ++t4) {
        const int tb = cs + t4 * TILE;
        const int gi = tb + tid;
        float4 pd;
        pd.x = x0p[gi]; pd.y = x1p[gi]; pd.z = x2p[gi]; pd.w = wp[gi];
        __syncthreads();            // previous tile fully consumed
        s_pt[tid] = pd;

        // ---- pass 1: own point's softmax denominator (no cross-lane ops) ----
        {
            float s0 = 0.f, s1 = 0.f, s2 = 0.f, s3 = 0.f;
            #pragma unroll 2
            for (int k = 0; k < K; k += 4) {
                float4 a = s_A[k + 0];
                float4 bb = s_A[k + 1];
                float4 c = s_A[k + 2];
                float4 d = s_A[k + 3];
                float t0 = fmaf(a.x,  pd.x, a.w);  t0 = fmaf(a.y,  pd.y, t0); t0 = fmaf(a.z,  pd.z, t0);
                float t1 = fmaf(bb.x, pd.x, bb.w); t1 = fmaf(bb.y, pd.y, t1); t1 = fmaf(bb.z, pd.z, t1);
                float t2 = fmaf(c.x,  pd.x, c.w);  t2 = fmaf(c.y,  pd.y, t2); t2 = fmaf(c.z,  pd.z, t2);
                float t3 = fmaf(d.x,  pd.x, d.w);  t3 = fmaf(d.y,  pd.y, t3); t3 = fmaf(d.z,  pd.z, t3);
                s0 += ex2f(t0); s1 += ex2f(t1); s2 += ex2f(t2); s3 += ex2f(t3);
            }
            s_v[tid] = __fdividef(pd.w, (s0 + s1) + (s2 + s3));
        }
        __syncthreads();            // tile points + v ready

        // ---- pass 2: cluster-per-lane accumulation ----
        #pragma unroll 8
        for (int m = 0; m < 32; ++m) {
            const int p = wid + m * 8;
            const float4 P = s_pt[p];
            const float  v = s_v[p];

            float t0 = fmaf(A0.x, P.x, A0.w); t0 = fmaf(A0.y, P.y, t0); t0 = fmaf(A0.z, P.z, t0);
            float t1 = fmaf(A1.x, P.x, A1.w); t1 = fmaf(A1.y, P.y, t1); t1 = fmaf(A1.z, P.z, t1);
            float t2 = fmaf(A2.x, P.x, A2.w); t2 = fmaf(A2.y, P.y, t2); t2 = fmaf(A2.z, P.z, t2);
            float t3 = fmaf(A3.x, P.x, A3.w); t3 = fmaf(A3.y, P.y, t3); t3 = fmaf(A3.z, P.z, t3);

            float g0 = ex2f(t0) * v, g1 = ex2f(t1) * v;
            float g2 = ex2f(t2) * v, g3 = ex2f(t3) * v;

            aD0 += g0; aX0 = fmaf(g0, P.x, aX0); aY0 = fmaf(g0, P.y, aY0); aZ0 = fmaf(g0, P.z, aZ0);
            aD1 += g1; aX1 = fmaf(g1, P.x, aX1); aY1 = fmaf(g1, P.y, aY1); aZ1 = fmaf(g1, P.z, aZ1);
            aD2 += g2; aX2 = fmaf(g2, P.x, aX2); aY2 = fmaf(g2, P.y, aY2); aZ2 = fmaf(g2, P.z, aZ2);
            aD3 += g3; aX3 = fmaf(g3, P.x, aX3); aY3 = fmaf(g3, P.y, aY3); aZ3 = fmaf(g3, P.z, aZ3);

            if (fin) {
                *(float4*)&out_gamma[((size_t)(b * N + tb + p)) * K + lane * 4]
                    = make_float4(g0, g1, g2, g3);
            }
        }
    }

    // -- block-level smem reduction of moments (stride-17 layout: lane*17 + j*4 + c) --
    {
        float* sm = &s_mom[lane * 17];
        atomicAdd(sm + 0,  aD0); atomicAdd(sm + 1,  aX0); atomicAdd(sm + 2,  aY0); atomicAdd(sm + 3,  aZ0);
        atomicAdd(sm + 4,  aD1); atomicAdd(sm + 5,  aX1); atomicAdd(sm + 6,  aY1); atomicAdd(sm + 7,  aZ1);
        atomicAdd(sm + 8,  aD2); atomicAdd(sm + 9,  aX2); atomicAdd(sm + 10, aY2); atomicAdd(sm + 11, aZ2);
        atomicAdd(sm + 12, aD3); atomicAdd(sm + 13, aX3); atomicAdd(sm + 14, aY3); atomicAdd(sm + 15, aZ3);
    }
    __syncthreads();

    // -- flush: one global atomic per (k,comp) per block; 2 per thread --
    {
        float* pb = &g_buf[it][b][0][0];
        #pragma unroll
        for (int r = 0; r < 2; ++r) {
            int t = tid + r * 256;                 // 0..511 = lane_src*16 + idx
            float val = s_mom[(t >> 4) * 17 + (t & 15)];
            atomicAdd(pb + t, val);                // global offset = (t>>4)*16 + (t&15) = t
        }
    }
}

// ---------------- kernel 4: finalize pi / node_xyz ----------------
__global__ void k_fin(float* __restrict__ out_pi, float* __restrict__ out_nxyz) {
    int b = blockIdx.x, k = threadIdx.x;   // <<<B, K>>>
    const float* pb = &g_buf[ITERS - 1][b][k][0];
    float raw = pb[0];
    float inv = 1.0f / (raw + EPS);
    out_pi[b * K + k] = raw / g_ssum[b];
    out_nxyz[(b * K + k) * 3 + 0] = pb[1] * inv;
    out_nxyz[(b * K + k) * 3 + 1] = pb[2] * inv;
    out_nxyz[(b * K + k) * 3 + 2] = pb[3] * inv;
}

// ---------------- kernel 5: node_feats = gamma^T @ feats (split-N, f32x2 FMA) ----------------
__global__ void __launch_bounds__(128)
k_nf(const float* __restrict__ feats, const float* __restrict__ gamma) {
    const int b  = blockIdx.y;
    const int n0 = blockIdx.x * (N / GEMM_CH);
    const int tid = threadIdx.x;
    const int k0 = (tid >> 3) * 8;   // 16 k-groups of 8
    const int d0 = (tid & 7) * 8;    // 8 d-groups of 8

    __shared__ float s_g[TN][K];          // 16 KB
    __shared__ float s_f[TN][D + FPAD];   // padded by 4 -> float4-aligned rows

    u64 acc[8][4];
    #pragma unroll
    for (int i = 0; i < 8; i++)
        #pragma unroll
        for (int c = 0; c < 4; c++) acc[i][c] = pack2(0.f, 0.f);

    const float* gbase = gamma + (size_t)b * N * K;
    const float* fbase = feats + (size_t)b * D * N;

    for (int t0 = n0; t0 < n0 + N / GEMM_CH; t0 += TN) {
        __syncthreads();
        {   // gamma tile: TN*K floats = 1024 float4, 8 per thread, coalesced
            const float4* src = (const float4*)(gbase + (size_t)t0 * K);
            float4* dst = (float4*)&s_g[0][0];
            #pragma unroll
            for (int j = 0; j < 8; j++) dst[tid + j * 128] = src[tid + j * 128];
        }
        {   // feats tile: D rows of TN consecutive n, transposed into s_f[n][d]
            #pragma unroll
            for (int j = 0; j < 16; j++) {
                int li = tid + j * 128;          // 0..2047
                int d = li >> 5, i = li & 31;
                s_f[i][d] = fbase[(size_t)d * N + t0 + i];
            }
        }
        __syncthreads();

        for (int i = 0; i < TN; i++) {
            float4 ga  = *(const float4*)&s_g[i][k0];
            float4 gb2 = *(const float4*)&s_g[i][k0 + 4];
            float4 fa  = *(const float4*)&s_f[i][d0];
            float4 fb  = *(const float4*)&s_f[i][d0 + 4];
            u64 f01 = pack2(fa.x, fa.y), f23 = pack2(fa.z, fa.w);
            u64 f45 = pack2(fb.x, fb.y), f67 = pack2(fb.z, fb.w);
            float gk[8] = {ga.x, ga.y, ga.z, ga.w, gb2.x, gb2.y, gb2.z, gb2.w};
            #pragma unroll
            for (int kk = 0; kk < 8; kk++) {
                u64 gg = pack2(gk[kk], gk[kk]);
                ffma2(acc[kk][0], gg, f01);
                ffma2(acc[kk][1], gg, f23);
                ffma2(acc[kk][2], gg, f45);
                ffma2(acc[kk][3], gg, f67);
            }
        }
    }

    #pragma unroll
    for (int kk = 0; kk < 8; kk++)
        #pragma unroll
        for (int c = 0; c < 4; c++) {
            float lo, hi; unpack2(acc[kk][c], lo, hi);
            float* dst = &g_nfacc[((size_t)b * K + (k0 + kk)) * D + d0 + c * 2];
            atomicAdd(dst, lo);
            atomicAdd(dst + 1, hi);
        }
}

// ---------------- kernel 6: divide node_feats by denom ----------------
__global__ void k_nf_fin(float* __restrict__ out_nf) {
    int i = blockIdx.x * blockDim.x + threadIdx.x;   // 65536 threads
    if (i < B * K * D) {
        int b = i / (K * D);
        int k = (i % (K * D)) / D;
        float dn = g_buf[ITERS - 1][b][k][0] + EPS;
        out_nf[i] = g_nfacc[i] / dn;
    }
}

// ---------------- launch ----------------
extern "C" void kernel_launch(void* const* d_in, const int* in_sizes, int n_in,
                              void* d_out, int out_size) {
    const float* xyz   = (const float*)d_in[0];
    const float* feats = (const float*)d_in[1];
    const float* osc   = (const float*)d_in[2];

    float* out   = (float*)d_out;
    float* ogam  = out;
    float* opi   = ogam + (size_t)B * N * K;
    float* oxyz  = opi + B * K;
    float* onf   = oxyz + B * K * 3;

    k_zero<<<256, 256>>>();
    k_init<<<B, 256>>>(xyz, osc);
    for (int it = 0; it < ITERS; ++it)
        k_iter<<<NB, 256>>>(xyz, osc, ogam, it);
    k_fin<<<B, K>>>(opi, oxyz);
    dim3 gg(GEMM_CH, B);
    k_nf<<<gg, 128>>>(feats, ogam);
    k_nf_fin<<<256, 256>>>(onf);
}

// round 15
// speedup vs baseline: 2.7708x; 1.0503x over previous
#include <cuda_runtime.h>
#include <cstdint>
#include <cstddef>

static constexpr int   B      = 8;
static constexpr int   N      = 32768;
static constexpr int   K      = 128;
static constexpr int   D      = 64;
static constexpr int   ITERS  = 10;
static constexpr float EPS    = 1e-8f;
static constexpr float LOG2E  = 1.4426950408889634f;

static constexpr int BPB   = 128;         // blocks per batch -> grid 1024, 1 tile per block
static constexpr int NB    = B * BPB;     // 1024 blocks
static constexpr int TILE  = 256;         // points per block (== chunk)

static constexpr int GEMM_CH = 64;        // n-chunks per batch for node_feats GEMM -> 512 blocks
static constexpr int TN      = 32;        // points per GEMM smem tile
static constexpr int FPAD    = 4;         // s_f row padding (keeps float4 alignment)

typedef unsigned long long u64;

// ---------------- device scratch (no allocations allowed) ----------------
__device__ float g_buf[ITERS][B][K][4];   // per-iter accumulators: denom, Mx, My, Mz
__device__ float g_cinit[B][K][3];
__device__ float g_ssum[B];
__device__ float g_nfacc[B * K * D];

// ---------------- small asm helpers ----------------
__device__ __forceinline__ float ex2f(float x) {
    float r; asm("ex2.approx.ftz.f32 %0, %1;" : "=f"(r) : "f"(x)); return r;
}
__device__ __forceinline__ u64 pack2(float lo, float hi) {
    u64 r; asm("mov.b64 %0, {%1, %2};" : "=l"(r) : "f"(lo), "f"(hi)); return r;
}
__device__ __forceinline__ void unpack2(u64 v, float& lo, float& hi) {
    asm("mov.b64 {%0, %1}, %2;" : "=f"(lo), "=f"(hi) : "l"(v));
}
__device__ __forceinline__ void ffma2(u64& d, u64 a, u64 b) {
    asm("fma.rn.f32x2 %0, %1, %2, %0;" : "+l"(d) : "l"(a), "l"(b));
}

// ---------------- kernel 1: zero scratch ----------------
__global__ void k_zero() {
    int i = blockIdx.x * blockDim.x + threadIdx.x;   // launched with 65536 threads
    float* gb = &g_buf[0][0][0][0];
    if (i < ITERS * B * K * 4) gb[i] = 0.f;
    if (i < B * K * D)         g_nfacc[i] = 0.f;
}

// ---------------- kernel 2: init centers + per-batch score sums ----------------
__global__ void k_init(const float* __restrict__ xyz, const float* __restrict__ osc) {
    int b = blockIdx.x, tid = threadIdx.x;
    __shared__ float red[256];
    const float* w = osc + (size_t)b * N;
    float s = 0.f;
    for (int n = tid; n < N; n += 256) s += w[n];
    red[tid] = s;
    __syncthreads();
    for (int st = 128; st > 0; st >>= 1) {
        if (tid < st) red[tid] += red[tid + st];
        __syncthreads();
    }
    if (tid == 0) g_ssum[b] = red[0] + EPS;
    if (tid < K) {
        int n0 = tid * (N / K);
        const float* xb = xyz + (size_t)b * 3 * N;
        g_cinit[b][tid][0] = xb[n0];
        g_cinit[b][tid][1] = xb[N + n0];
        g_cinit[b][tid][2] = xb[2 * N + n0];
    }
}

// ---------------- kernel 3: one clustering iteration (launched ITERS times) ----------------
// One 256-point tile per block. Two-pass softmax; register liveness staged so that
// A0-A3 and the 16 moment accumulators are NOT live during pass 1 (fits 64-reg cap).
template <bool FIN>
__global__ void __launch_bounds__(256, 4)
k_iter(const float* __restrict__ xyz, const float* __restrict__ osc,
       float* __restrict__ out_gamma, int it) {
    const int b    = blockIdx.x >> 7;         // / BPB (=128)
    const int slot = blockIdx.x & (BPB - 1);
    const int tb   = slot * TILE;
    const int tid  = threadIdx.x;
    const int lane = tid & 31;
    const int wid  = tid >> 5;

    __shared__ float4 s_A[K];          // center constants (2*log2e*c, -log2e*|c|^2)
    __shared__ float4 s_pt[TILE];      // staged points: x0,x1,x2,w
    __shared__ float  s_v[TILE];       // per-point w/s (softmax scale)
    __shared__ float  s_mom[32 * 17];  // block moment reduction, stride-17 (conflict-free)

    const float* x0p = xyz + (size_t)b * 3 * N;

    // -- stage tile + zero moment scratch + derive A_k (one sync for all) --
    const int gi = tb + tid;
    float4 pd;
    pd.x = x0p[gi]; pd.y = x0p[N + gi]; pd.z = x0p[2 * N + gi];
    pd.w = osc[(size_t)b * N + gi];
    s_pt[tid] = pd;
    s_mom[tid] = 0.f;
    s_mom[tid + 256] = 0.f;
    if (tid < 32) s_mom[tid + 512] = 0.f;
    if (tid < K) {
        float c0, c1, c2;
        if (it == 0) {
            c0 = g_cinit[b][tid][0];
            c1 = g_cinit[b][tid][1];
            c2 = g_cinit[b][tid][2];
        } else {
            const float* pb = &g_buf[it - 1][b][tid][0];
            float inv = 1.0f / (pb[0] + EPS);
            c0 = pb[1] * inv; c1 = pb[2] * inv; c2 = pb[3] * inv;
        }
        s_A[tid] = make_float4(2.f * LOG2E * c0, 2.f * LOG2E * c1, 2.f * LOG2E * c2,
                               -LOG2E * (c0 * c0 + c1 * c1 + c2 * c2));
    }
    __syncthreads();

    // ---- pass 1: own point's softmax denominator (no cross-lane ops) ----
    {
        float s0 = 0.f, s1 = 0.f, s2 = 0.f, s3 = 0.f;
        #pragma unroll 2
        for (int k = 0; k < K; k += 4) {
            float4 a = s_A[k + 0];
            float4 bb = s_A[k + 1];
            float4 c = s_A[k + 2];
            float4 d = s_A[k + 3];
            float t0 = fmaf(a.x,  pd.x, a.w);  t0 = fmaf(a.y,  pd.y, t0); t0 = fmaf(a.z,  pd.z, t0);
            float t1 = fmaf(bb.x, pd.x, bb.w); t1 = fmaf(bb.y, pd.y, t1); t1 = fmaf(bb.z, pd.z, t1);
            float t2 = fmaf(c.x,  pd.x, c.w);  t2 = fmaf(c.y,  pd.y, t2); t2 = fmaf(c.z,  pd.z, t2);
            float t3 = fmaf(d.x,  pd.x, d.w);  t3 = fmaf(d.y,  pd.y, t3); t3 = fmaf(d.z,  pd.z, t3);
            s0 += ex2f(t0); s1 += ex2f(t1); s2 += ex2f(t2); s3 += ex2f(t3);
        }
        s_v[tid] = __fdividef(pd.w, (s0 + s1) + (s2 + s3));
    }
    __syncthreads();            // tile v ready

    // ---- pass 2: cluster-per-lane accumulation (A + acc become live only now) ----
    const float4 A0 = s_A[lane * 4 + 0];
    const float4 A1 = s_A[lane * 4 + 1];
    const float4 A2 = s_A[lane * 4 + 2];
    const float4 A3 = s_A[lane * 4 + 3];

    float aD0 = 0.f, aD1 = 0.f, aD2 = 0.f, aD3 = 0.f;
    float aX0 = 0.f, aX1 = 0.f, aX2 = 0.f, aX3 = 0.f;
    float aY0 = 0.f, aY1 = 0.f, aY2 = 0.f, aY3 = 0.f;
    float aZ0 = 0.f, aZ1 = 0.f, aZ2 = 0.f, aZ3 = 0.f;

    #pragma unroll 8
    for (int m = 0; m < 32; ++m) {
        const int p = wid + m * 8;
        const float4 P = s_pt[p];
        const float  v = s_v[p];

        float t0 = fmaf(A0.x, P.x, A0.w); t0 = fmaf(A0.y, P.y, t0); t0 = fmaf(A0.z, P.z, t0);
        float t1 = fmaf(A1.x, P.x, A1.w); t1 = fmaf(A1.y, P.y, t1); t1 = fmaf(A1.z, P.z, t1);
        float t2 = fmaf(A2.x, P.x, A2.w); t2 = fmaf(A2.y, P.y, t2); t2 = fmaf(A2.z, P.z, t2);
        float t3 = fmaf(A3.x, P.x, A3.w); t3 = fmaf(A3.y, P.y, t3); t3 = fmaf(A3.z, P.z, t3);

        float g0 = ex2f(t0) * v, g1 = ex2f(t1) * v;
        float g2 = ex2f(t2) * v, g3 = ex2f(t3) * v;

        aD0 += g0; aX0 = fmaf(g0, P.x, aX0); aY0 = fmaf(g0, P.y, aY0); aZ0 = fmaf(g0, P.z, aZ0);
        aD1 += g1; aX1 = fmaf(g1, P.x, aX1); aY1 = fmaf(g1, P.y, aY1); aZ1 = fmaf(g1, P.z, aZ1);
        aD2 += g2; aX2 = fmaf(g2, P.x, aX2); aY2 = fmaf(g2, P.y, aY2); aZ2 = fmaf(g2, P.z, aZ2);
        aD3 += g3; aX3 = fmaf(g3, P.x, aX3); aY3 = fmaf(g3, P.y, aY3); aZ3 = fmaf(g3, P.z, aZ3);

        if (FIN) {
            *(float4*)&out_gamma[((size_t)(b * N + tb + p)) * K + lane * 4]
                = make_float4(g0, g1, g2, g3);
        }
    }

    // -- block-level smem reduction of moments (stride-17 layout: lane*17 + idx) --
    {
        float* sm = &s_mom[lane * 17];
        atomicAdd(sm + 0,  aD0); atomicAdd(sm + 1,  aX0); atomicAdd(sm + 2,  aY0); atomicAdd(sm + 3,  aZ0);
        atomicAdd(sm + 4,  aD1); atomicAdd(sm + 5,  aX1); atomicAdd(sm + 6,  aY1); atomicAdd(sm + 7,  aZ1);
        atomicAdd(sm + 8,  aD2); atomicAdd(sm + 9,  aX2); atomicAdd(sm + 10, aY2); atomicAdd(sm + 11, aZ2);
        atomicAdd(sm + 12, aD3); atomicAdd(sm + 13, aX3); atomicAdd(sm + 14, aY3); atomicAdd(sm + 15, aZ3);
    }
    __syncthreads();

    // -- flush: one global atomic per (k,comp) per block; 2 per thread --
    {
        float* pb = &g_buf[it][b][0][0];
        #pragma unroll
        for (int r = 0; r < 2; ++r) {
            int t = tid + r * 256;                 // 0..511 = lane_src*16 + idx
            float val = s_mom[(t >> 4) * 17 + (t & 15)];
            atomicAdd(pb + t, val);                // global offset = (t>>4)*16 + (t&15) = t
        }
    }
}

// ---------------- kernel 4: finalize pi / node_xyz ----------------
__global__ void k_fin(float* __restrict__ out_pi, float* __restrict__ out_nxyz) {
    int b = blockIdx.x, k = threadIdx.x;   // <<<B, K>>>
    const float* pb = &g_buf[ITERS - 1][b][k][0];
    float raw = pb[0];
    float inv = 1.0f / (raw + EPS);
    out_pi[b * K + k] = raw / g_ssum[b];
    out_nxyz[(b * K + k) * 3 + 0] = pb[1] * inv;
    out_nxyz[(b * K + k) * 3 + 1] = pb[2] * inv;
    out_nxyz[(b * K + k) * 3 + 2] = pb[3] * inv;
}

// ---------------- kernel 5: node_feats = gamma^T @ feats (split-N, f32x2 FMA) ----------------
__global__ void __launch_bounds__(128)
k_nf(const float* __restrict__ feats, const float* __restrict__ gamma) {
    const int b  = blockIdx.y;
    const int n0 = blockIdx.x * (N / GEMM_CH);
    const int tid = threadIdx.x;
    const int k0 = (tid >> 3) * 8;   // 16 k-groups of 8
    const int d0 = (tid & 7) * 8;    // 8 d-groups of 8

    __shared__ float s_g[TN][K];          // 16 KB
    __shared__ float s_f[TN][D + FPAD];   // padded by 4 -> float4-aligned rows

    u64 acc[8][4];
    #pragma unroll
    for (int i = 0; i < 8; i++)
        #pragma unroll
        for (int c = 0; c < 4; c++) acc[i][c] = pack2(0.f, 0.f);

    const float* gbase = gamma + (size_t)b * N * K;
    const float* fbase = feats + (size_t)b * D * N;

    for (int t0 = n0; t0 < n0 + N / GEMM_CH; t0 += TN) {
        __syncthreads();
        {   // gamma tile: TN*K floats = 1024 float4, 8 per thread, coalesced
            const float4* src = (const float4*)(gbase + (size_t)t0 * K);
            float4* dst = (float4*)&s_g[0][0];
            #pragma unroll
            for (int j = 0; j < 8; j++) dst[tid + j * 128] = src[tid + j * 128];
        }
        {   // feats tile: D rows of TN consecutive n, transposed into s_f[n][d]
            #pragma unroll
            for (int j = 0; j < 16; j++) {
                int li = tid + j * 128;          // 0..2047
                int d = li >> 5, i = li & 31;
                s_f[i][d] = fbase[(size_t)d * N + t0 + i];
            }
        }
        __syncthreads();

        for (int i = 0; i < TN; i++) {
            float4 ga  = *(const float4*)&s_g[i][k0];
            float4 gb2 = *(const float4*)&s_g[i][k0 + 4];
            float4 fa  = *(const float4*)&s_f[i][d0];
            float4 fb  = *(const float4*)&s_f[i][d0 + 4];
            u64 f01 = pack2(fa.x, fa.y), f23 = pack2(fa.z, fa.w);
            u64 f45 = pack2(fb.x, fb.y), f67 = pack2(fb.z, fb.w);
            float gk[8] = {ga.x, ga.y, ga.z, ga.w, gb2.x, gb2.y, gb2.z, gb2.w};
            #pragma unroll
            for (int kk = 0; kk < 8; kk++) {
                u64 gg = pack2(gk[kk], gk[kk]);
                ffma2(acc[kk][0], gg, f01);
                ffma2(acc[kk][1], gg, f23);
                ffma2(acc[kk][2], gg, f45);
                ffma2(acc[kk][3], gg, f67);
            }
        }
    }

    #pragma unroll
    for (int kk = 0; kk < 8; kk++)
        #pragma unroll
        for (int c = 0; c < 4; c++) {
            float lo, hi; unpack2(acc[kk][c], lo, hi);
            float* dst = &g_nfacc[((size_t)b * K + (k0 + kk)) * D + d0 + c * 2];
            atomicAdd(dst, lo);
            atomicAdd(dst + 1, hi);
        }
}

// ---------------- kernel 6: divide node_feats by denom ----------------
__global__ void k_nf_fin(float* __restrict__ out_nf) {
    int i = blockIdx.x * blockDim.x + threadIdx.x;   // 65536 threads
    if (i < B * K * D) {
        int b = i / (K * D);
        int k = (i % (K * D)) / D;
        float dn = g_buf[ITERS - 1][b][k][0] + EPS;
        out_nf[i] = g_nfacc[i] / dn;
    }
}

// ---------------- launch ----------------
extern "C" void kernel_launch(void* const* d_in, const int* in_sizes, int n_in,
                              void* d_out, int out_size) {
    const float* xyz   = (const float*)d_in[0];
    const float* feats = (const float*)d_in[1];
    const float* osc   = (const float*)d_in[2];

    float* out   = (float*)d_out;
    float* ogam  = out;
    float* opi   = ogam + (size_t)B * N * K;
    float* oxyz  = opi + B * K;
    float* onf   = oxyz + B * K * 3;

    k_zero<<<256, 256>>>();
    k_init<<<B, 256>>>(xyz, osc);
    for (int it = 0; it < ITERS - 1; ++it)
        k_iter<false><<<NB, 256>>>(xyz, osc, ogam, it);
    k_iter<true><<<NB, 256>>>(xyz, osc, ogam, ITERS - 1);
    k_fin<<<B, K>>>(opi, oxyz);
    dim3 gg(GEMM_CH, B);
    k_nf<<<gg, 128>>>(feats, ogam);
    k_nf_fin<<<256, 256>>>(onf);
}

// round 16
// speedup vs baseline: 3.0464x; 1.0995x over previous
#include <cuda_runtime.h>
#include <cstdint>
#include <cstddef>

static constexpr int   B      = 8;
static constexpr int   N      = 32768;
static constexpr int   K      = 128;
static constexpr int   D      = 64;
static constexpr int   ITERS  = 10;
static constexpr float EPS    = 1e-8f;
static constexpr float LOG2E  = 1.4426950408889634f;

static constexpr int BPB   = 128;         // blocks per batch -> grid 1024, 1 tile per block
static constexpr int NB    = B * BPB;     // 1024 blocks
static constexpr int TILE  = 256;         // points per block (== chunk)

static constexpr int GEMM_CH = 64;        // n-chunks per batch for node_feats GEMM -> 512 blocks
static constexpr int TN      = 32;        // points per GEMM smem tile
static constexpr int FPAD    = 4;         // s_f row padding (keeps float4 alignment)

typedef unsigned long long u64;

// ---------------- device scratch (no allocations allowed) ----------------
__device__ float g_buf[ITERS][B][K][4];   // per-iter accumulators: denom, Mx, My, Mz
__device__ float g_cinit[B][K][3];
__device__ float g_ssum[B];
__device__ float g_nfacc[B * K * D];

// ---------------- small asm helpers ----------------
__device__ __forceinline__ float ex2f(float x) {
    float r; asm("ex2.approx.ftz.f32 %0, %1;" : "=f"(r) : "f"(x)); return r;
}
__device__ __forceinline__ u64 pack2(float lo, float hi) {
    u64 r; asm("mov.b64 %0, {%1, %2};" : "=l"(r) : "f"(lo), "f"(hi)); return r;
}
__device__ __forceinline__ void unpack2(u64 v, float& lo, float& hi) {
    asm("mov.b64 {%0, %1}, %2;" : "=f"(lo), "=f"(hi) : "l"(v));
}
__device__ __forceinline__ void ffma2(u64& d, u64 a, u64 b) {
    asm("fma.rn.f32x2 %0, %1, %2, %0;" : "+l"(d) : "l"(a), "l"(b));
}

// ---------------- kernel 1: init (zero scratch + centers + score sums, fused) ----------------
__global__ void k_init(const float* __restrict__ xyz, const float* __restrict__ osc) {
    const int tid = threadIdx.x;
    const int gidx = blockIdx.x * 256 + tid;       // grid 256 -> 65536 threads

    // zero stripes of scratch
    float* gb = &g_buf[0][0][0][0];
    if (gidx < ITERS * B * K * 4) gb[gidx] = 0.f;
    if (gidx < B * K * D)         g_nfacc[gidx] = 0.f;

    // blocks 0..B-1 additionally do per-batch init
    if (blockIdx.x < B) {
        const int b = blockIdx.x;
        __shared__ float red[256];
        const float* w = osc + (size_t)b * N;
        float s = 0.f;
        for (int n = tid; n < N; n += 256) s += w[n];
        red[tid] = s;
        __syncthreads();
        for (int st = 128; st > 0; st >>= 1) {
            if (tid < st) red[tid] += red[tid + st];
            __syncthreads();
        }
        if (tid == 0) g_ssum[b] = red[0] + EPS;
        if (tid < K) {
            int n0 = tid * (N / K);
            const float* xb = xyz + (size_t)b * 3 * N;
            g_cinit[b][tid][0] = xb[n0];
            g_cinit[b][tid][1] = xb[N + n0];
            g_cinit[b][tid][2] = xb[2 * N + n0];
        }
    }
}

// ---------------- kernel 2: one clustering iteration (launched ITERS times) ----------------
// Single-pass shuffle softmax inside the R15 shell: one 256-point tile per block,
// cluster-per-lane, 5-level butterfly per point (EX2 computed ONCE per (n,k)),
// block-level smem moment reduction before global atomics.
template <bool FIN>
__global__ void __launch_bounds__(256, 4)
k_iter(const float* __restrict__ xyz, const float* __restrict__ osc,
       float* __restrict__ out_gamma, int it) {
    const int b    = blockIdx.x >> 7;         // / BPB (=128)
    const int slot = blockIdx.x & (BPB - 1);
    const int tb   = slot * TILE;
    const int tid  = threadIdx.x;
    const int lane = tid & 31;
    const int wid  = tid >> 5;

    __shared__ float4 s_A[K];          // center constants (2*log2e*c, -log2e*|c|^2)
    __shared__ float4 s_pt[TILE];      // staged points: x0,x1,x2,w
    __shared__ float  s_mom[32 * 17];  // block moment reduction, stride-17 (conflict-free)

    const float* x0p = xyz + (size_t)b * 3 * N;

    // -- stage tile + zero moment scratch + derive A_k (one sync for all) --
    const int gi = tb + tid;
    float4 pd;
    pd.x = x0p[gi]; pd.y = x0p[N + gi]; pd.z = x0p[2 * N + gi];
    pd.w = osc[(size_t)b * N + gi];
    s_pt[tid] = pd;
    s_mom[tid] = 0.f;
    s_mom[tid + 256] = 0.f;
    if (tid < 32) s_mom[tid + 512] = 0.f;
    if (tid < K) {
        float c0, c1, c2;
        if (it == 0) {
            c0 = g_cinit[b][tid][0];
            c1 = g_cinit[b][tid][1];
            c2 = g_cinit[b][tid][2];
        } else {
            const float* pb = &g_buf[it - 1][b][tid][0];
            float inv = 1.0f / (pb[0] + EPS);
            c0 = pb[1] * inv; c1 = pb[2] * inv; c2 = pb[3] * inv;
        }
        s_A[tid] = make_float4(2.f * LOG2E * c0, 2.f * LOG2E * c1, 2.f * LOG2E * c2,
                               -LOG2E * (c0 * c0 + c1 * c1 + c2 * c2));
    }
    __syncthreads();

    // each lane owns 4 consecutive clusters
    const float4 A0 = s_A[lane * 4 + 0];
    const float4 A1 = s_A[lane * 4 + 1];
    const float4 A2 = s_A[lane * 4 + 2];
    const float4 A3 = s_A[lane * 4 + 3];

    float aD0 = 0.f, aD1 = 0.f, aD2 = 0.f, aD3 = 0.f;
    float aX0 = 0.f, aX1 = 0.f, aX2 = 0.f, aX3 = 0.f;
    float aY0 = 0.f, aY1 = 0.f, aY2 = 0.f, aY3 = 0.f;
    float aZ0 = 0.f, aZ1 = 0.f, aZ2 = 0.f, aZ3 = 0.f;

    #pragma unroll 8
    for (int m = 0; m < 32; ++m) {
        const int p = wid + m * 8;
        const float4 P = s_pt[p];

        float t0 = fmaf(A0.x, P.x, A0.w); t0 = fmaf(A0.y, P.y, t0); t0 = fmaf(A0.z, P.z, t0);
        float t1 = fmaf(A1.x, P.x, A1.w); t1 = fmaf(A1.y, P.y, t1); t1 = fmaf(A1.z, P.z, t1);
        float t2 = fmaf(A2.x, P.x, A2.w); t2 = fmaf(A2.y, P.y, t2); t2 = fmaf(A2.z, P.z, t2);
        float t3 = fmaf(A3.x, P.x, A3.w); t3 = fmaf(A3.y, P.y, t3); t3 = fmaf(A3.z, P.z, t3);

        const float e0 = ex2f(t0), e1 = ex2f(t1), e2 = ex2f(t2), e3 = ex2f(t3);
        float s = (e0 + e1) + (e2 + e3);
        #pragma unroll
        for (int o = 16; o > 0; o >>= 1) s += __shfl_xor_sync(0xffffffffu, s, o);

        const float u = __fdividef(P.w, s);
        const float g0 = e0 * u, g1 = e1 * u, g2 = e2 * u, g3 = e3 * u;

        aD0 += g0; aX0 = fmaf(g0, P.x, aX0); aY0 = fmaf(g0, P.y, aY0); aZ0 = fmaf(g0, P.z, aZ0);
        aD1 += g1; aX1 = fmaf(g1, P.x, aX1); aY1 = fmaf(g1, P.y, aY1); aZ1 = fmaf(g1, P.z, aZ1);
        aD2 += g2; aX2 = fmaf(g2, P.x, aX2); aY2 = fmaf(g2, P.y, aY2); aZ2 = fmaf(g2, P.z, aZ2);
        aD3 += g3; aX3 = fmaf(g3, P.x, aX3); aY3 = fmaf(g3, P.y, aY3); aZ3 = fmaf(g3, P.z, aZ3);

        if (FIN) {
            *(float4*)&out_gamma[((size_t)(b * N + tb + p)) * K + lane * 4]
                = make_float4(g0, g1, g2, g3);
        }
    }

    // -- block-level smem reduction of moments (stride-17 layout: lane*17 + idx) --
    {
        float* sm = &s_mom[lane * 17];
        atomicAdd(sm + 0,  aD0); atomicAdd(sm + 1,  aX0); atomicAdd(sm + 2,  aY0); atomicAdd(sm + 3,  aZ0);
        atomicAdd(sm + 4,  aD1); atomicAdd(sm + 5,  aX1); atomicAdd(sm + 6,  aY1); atomicAdd(sm + 7,  aZ1);
        atomicAdd(sm + 8,  aD2); atomicAdd(sm + 9,  aX2); atomicAdd(sm + 10, aY2); atomicAdd(sm + 11, aZ2);
        atomicAdd(sm + 12, aD3); atomicAdd(sm + 13, aX3); atomicAdd(sm + 14, aY3); atomicAdd(sm + 15, aZ3);
    }
    __syncthreads();

    // -- flush: one global atomic per (k,comp) per block; 2 per thread --
    {
        float* pb = &g_buf[it][b][0][0];
        #pragma unroll
        for (int r = 0; r < 2; ++r) {
            int t = tid + r * 256;                 // 0..511 = lane_src*16 + idx
            float val = s_mom[(t >> 4) * 17 + (t & 15)];
            atomicAdd(pb + t, val);                // global offset = (t>>4)*16 + (t&15) = t
        }
    }
}

// ---------------- kernel 3: node_feats = gamma^T @ feats (split-N, f32x2 FMA) ----------------
__global__ void __launch_bounds__(128)
k_nf(const float* __restrict__ feats, const float* __restrict__ gamma) {
    const int b  = blockIdx.y;
    const int n0 = blockIdx.x * (N / GEMM_CH);
    const int tid = threadIdx.x;
    const int k0 = (tid >> 3) * 8;   // 16 k-groups of 8
    const int d0 = (tid & 7) * 8;    // 8 d-groups of 8

    __shared__ float s_g[TN][K];          // 16 KB
    __shared__ float s_f[TN][D + FPAD];   // padded by 4 -> float4-aligned rows

    u64 acc[8][4];
    #pragma unroll
    for (int i = 0; i < 8; i++)
        #pragma unroll
        for (int c = 0; c < 4; c++) acc[i][c] = pack2(0.f, 0.f);

    const float* gbase = gamma + (size_t)b * N * K;
    const float* fbase = feats + (size_t)b * D * N;

    for (int t0 = n0; t0 < n0 + N / GEMM_CH; t0 += TN) {
        __syncthreads();
        {   // gamma tile: TN*K floats = 1024 float4, 8 per thread, coalesced
            const float4* src = (const float4*)(gbase + (size_t)t0 * K);
            float4* dst = (float4*)&s_g[0][0];
            #pragma unroll
            for (int j = 0; j < 8; j++) dst[tid + j * 128] = src[tid + j * 128];
        }
        {   // feats tile: D rows of TN consecutive n, transposed into s_f[n][d]
            #pragma unroll
            for (int j = 0; j < 16; j++) {
                int li = tid + j * 128;          // 0..2047
                int d = li >> 5, i = li & 31;
                s_f[i][d] = fbase[(size_t)d * N + t0 + i];
            }
        }
        __syncthreads();

        for (int i = 0; i < TN; i++) {
            float4 ga  = *(const float4*)&s_g[i][k0];
            float4 gb2 = *(const float4*)&s_g[i][k0 + 4];
            float4 fa  = *(const float4*)&s_f[i][d0];
            float4 fb  = *(const float4*)&s_f[i][d0 + 4];
            u64 f01 = pack2(fa.x, fa.y), f23 = pack2(fa.z, fa.w);
            u64 f45 = pack2(fb.x, fb.y), f67 = pack2(fb.z, fb.w);
            float gk[8] = {ga.x, ga.y, ga.z, ga.w, gb2.x, gb2.y, gb2.z, gb2.w};
            #pragma unroll
            for (int kk = 0; kk < 8; kk++) {
                u64 gg = pack2(gk[kk], gk[kk]);
                ffma2(acc[kk][0], gg, f01);
                ffma2(acc[kk][1], gg, f23);
                ffma2(acc[kk][2], gg, f45);
                ffma2(acc[kk][3], gg, f67);
            }
        }
    }

    #pragma unroll
    for (int kk = 0; kk < 8; kk++)
        #pragma unroll
        for (int c = 0; c < 4; c++) {
            float lo, hi; unpack2(acc[kk][c], lo, hi);
            float* dst = &g_nfacc[((size_t)b * K + (k0 + kk)) * D + d0 + c * 2];
            atomicAdd(dst, lo);
            atomicAdd(dst + 1, hi);
        }
}

// ---------------- kernel 4: finalize node_feats + pi + node_xyz (fused) ----------------
__global__ void k_nf_fin(float* __restrict__ out_nf, float* __restrict__ out_pi,
                         float* __restrict__ out_nxyz) {
    int i = blockIdx.x * blockDim.x + threadIdx.x;   // 65536 threads
    if (i < B * K * D) {
        int b = i / (K * D);
        int k = (i % (K * D)) / D;
        float dn = g_buf[ITERS - 1][b][k][0] + EPS;
        out_nf[i] = g_nfacc[i] / dn;
    }
    if (i < B * K) {
        int b = i / K, k = i % K;
        const float* pb = &g_buf[ITERS - 1][b][k][0];
        float raw = pb[0];
        float inv = 1.0f / (raw + EPS);
        out_pi[i] = raw / g_ssum[b];
        out_nxyz[i * 3 + 0] = pb[1] * inv;
        out_nxyz[i * 3 + 1] = pb[2] * inv;
        out_nxyz[i * 3 + 2] = pb[3] * inv;
    }
}

// ---------------- launch ----------------
extern "C" void kernel_launch(void* const* d_in, const int* in_sizes, int n_in,
                              void* d_out, int out_size) {
    const float* xyz   = (const float*)d_in[0];
    const float* feats = (const float*)d_in[1];
    const float* osc   = (const float*)d_in[2];

    float* out   = (float*)d_out;
    float* ogam  = out;
    float* opi   = ogam + (size_t)B * N * K;
    float* oxyz  = opi + B * K;
    float* onf   = oxyz + B * K * 3;

    k_init<<<256, 256>>>(xyz, osc);
    for (int it = 0; it < ITERS - 1; ++it)
        k_iter<false><<<NB, 256>>>(xyz, osc, ogam, it);
    k_iter<true><<<NB, 256>>>(xyz, osc, ogam, ITERS - 1);
    dim3 gg(GEMM_CH, B);
    k_nf<<<gg, 128>>>(feats, ogam);
    k_nf_fin<<<256, 256>>>(onf, opi, oxyz);
}